// round 1
// baseline (speedup 1.0000x reference)
#include <cuda_runtime.h>
#include <cuda_bf16.h>
#include <math.h>

// ---------------------------------------------------------------------------
// Problem constants
// ---------------------------------------------------------------------------
#define BATCH 16
#define SEQ 256
#define NTOK (BATCH * SEQ)          // 4096
#define HID 768
#define NHEAD 12
#define HDIM 64
#define FFN 3072
#define NLAYER 6
#define NTAGS 9

// ---------------------------------------------------------------------------
// Scratch (device globals; no allocation allowed)
// ---------------------------------------------------------------------------
__device__ float g_x[NTOK * HID];        // activations
__device__ float g_qkv[NTOK * 3 * HID];  // qkv projection
__device__ float g_attn[NTOK * HID];     // attention output
__device__ float g_ffn[NTOK * FFN];      // ffn intermediate
__device__ float g_tmp[NTOK * HID];      // gemm output pre-residual
__device__ float g_nmd[BATCH];           // per-sequence (num - denom)

// ---------------------------------------------------------------------------
// Block reduction helper (blockDim.x == 256)
// ---------------------------------------------------------------------------
__device__ __forceinline__ float block_reduce_sum(float v, float* red) {
    int t = threadIdx.x;
    red[t] = v;
    __syncthreads();
    #pragma unroll
    for (int s = 128; s > 0; s >>= 1) {
        if (t < s) red[t] += red[t + s];
        __syncthreads();
    }
    float r = red[0];
    __syncthreads();
    return r;
}

// ---------------------------------------------------------------------------
// Embedding + LayerNorm : x[row] = LN(word_emb[id] + pos_emb[s])
// grid = NTOK, block = 256
// ---------------------------------------------------------------------------
__global__ __launch_bounds__(256) void embed_ln_kernel(
    const int* __restrict__ ids, const float* __restrict__ wemb,
    const float* __restrict__ pemb, const float* __restrict__ lns,
    const float* __restrict__ lnb, float* __restrict__ xout)
{
    __shared__ float red[256];
    int row = blockIdx.x;
    int spos = row & (SEQ - 1);
    int id = ids[row];
    int t = threadIdx.x;

    float v[3];
    #pragma unroll
    for (int i = 0; i < 3; i++) {
        int c = t + i * 256;
        v[i] = wemb[(size_t)id * HID + c] + pemb[(size_t)spos * HID + c];
    }
    float sum = v[0] + v[1] + v[2];
    float mean = block_reduce_sum(sum, red) * (1.0f / HID);
    float sq = 0.f;
    #pragma unroll
    for (int i = 0; i < 3; i++) { float d = v[i] - mean; sq += d * d; }
    float var = block_reduce_sum(sq, red) * (1.0f / HID);
    float inv = rsqrtf(var + 1e-12f);
    #pragma unroll
    for (int i = 0; i < 3; i++) {
        int c = t + i * 256;
        xout[(size_t)row * HID + c] = (v[i] - mean) * inv * lns[c] + lnb[c];
    }
}

// ---------------------------------------------------------------------------
// Residual + LayerNorm : x[row] = LN(x[row] + y[row]) * s + b
// ---------------------------------------------------------------------------
__global__ __launch_bounds__(256) void resid_ln_kernel(
    float* __restrict__ x, const float* __restrict__ y,
    const float* __restrict__ lns, const float* __restrict__ lnb)
{
    __shared__ float red[256];
    int row = blockIdx.x;
    int t = threadIdx.x;
    float v[3];
    #pragma unroll
    for (int i = 0; i < 3; i++) {
        int c = t + i * 256;
        v[i] = x[(size_t)row * HID + c] + y[(size_t)row * HID + c];
    }
    float sum = v[0] + v[1] + v[2];
    float mean = block_reduce_sum(sum, red) * (1.0f / HID);
    float sq = 0.f;
    #pragma unroll
    for (int i = 0; i < 3; i++) { float d = v[i] - mean; sq += d * d; }
    float var = block_reduce_sum(sq, red) * (1.0f / HID);
    float inv = rsqrtf(var + 1e-12f);
    #pragma unroll
    for (int i = 0; i < 3; i++) {
        int c = t + i * 256;
        x[(size_t)row * HID + c] = (v[i] - mean) * inv * lns[c] + lnb[c];
    }
}

// ---------------------------------------------------------------------------
// fp32 GEMM: C[M,N] = A[M,K] @ B[K,N] + bias[N]  (optional gelu)
// 128x128 block tile, BK=8, 256 threads, 8x8 per thread.
// Requires M%128==0, N%128==0, K%8==0.
// ---------------------------------------------------------------------------
#define BM 128
#define BN 128
#define BK 8

__device__ __forceinline__ float gelu_tanh(float v) {
    float c = 0.7978845608028654f;  // sqrt(2/pi)
    float u = c * (v + 0.044715f * v * v * v);
    return 0.5f * v * (1.0f + tanhf(u));
}

__global__ __launch_bounds__(256) void sgemm_kernel(
    const float* __restrict__ A, const float* __restrict__ B,
    const float* __restrict__ bias, float* __restrict__ C,
    int M, int N, int K, int act)
{
    __shared__ float As[BK][BM];
    __shared__ float Bs[BK][BN];

    int bx = blockIdx.x;     // N tile
    int by = blockIdx.y;     // M tile
    int t = threadIdx.x;
    int tx = t & 15;
    int ty = t >> 4;

    int aRow = t >> 1;             // 0..127
    int aCol = (t & 1) * 4;        // 0 or 4
    int bRow = t >> 5;             // 0..7
    int bCol = (t & 31) * 4;       // 0..124

    const float* Abase = A + (size_t)by * BM * K;

    float acc[8][8];
    #pragma unroll
    for (int i = 0; i < 8; i++)
        #pragma unroll
        for (int j = 0; j < 8; j++) acc[i][j] = 0.f;

    for (int k0 = 0; k0 < K; k0 += BK) {
        float4 av = *reinterpret_cast<const float4*>(Abase + (size_t)aRow * K + k0 + aCol);
        As[aCol + 0][aRow] = av.x;
        As[aCol + 1][aRow] = av.y;
        As[aCol + 2][aRow] = av.z;
        As[aCol + 3][aRow] = av.w;
        float4 bv = *reinterpret_cast<const float4*>(B + (size_t)(k0 + bRow) * N + bx * BN + bCol);
        *reinterpret_cast<float4*>(&Bs[bRow][bCol]) = bv;
        __syncthreads();

        #pragma unroll
        for (int kk = 0; kk < BK; kk++) {
            float a[8], b[8];
            #pragma unroll
            for (int i = 0; i < 8; i++) a[i] = As[kk][ty * 8 + i];
            #pragma unroll
            for (int j = 0; j < 8; j++) b[j] = Bs[kk][tx * 8 + j];
            #pragma unroll
            for (int i = 0; i < 8; i++)
                #pragma unroll
                for (int j = 0; j < 8; j++)
                    acc[i][j] += a[i] * b[j];
        }
        __syncthreads();
    }

    #pragma unroll
    for (int i = 0; i < 8; i++) {
        int row = by * BM + ty * 8 + i;
        int colb = bx * BN + tx * 8;
        #pragma unroll
        for (int j = 0; j < 8; j++) {
            float v = acc[i][j] + bias[colb + j];
            if (act == 1) v = gelu_tanh(v);
            C[(size_t)row * N + colb + j] = v;
        }
    }
}

// ---------------------------------------------------------------------------
// Fused attention: one block per (b, h). 256 threads = 256 query rows.
// K,V for the head staged in SMEM (128KB); two-pass softmax, scores in local.
// ---------------------------------------------------------------------------
#define ATTN_SMEM (2 * SEQ * HDIM * 4 + SEQ * 4)

__global__ __launch_bounds__(256) void attn_kernel(
    const float* __restrict__ qkv, const int* __restrict__ amask,
    float* __restrict__ out)
{
    extern __shared__ float sh[];
    float* Ks = sh;                  // [256][64]
    float* Vs = sh + SEQ * HDIM;     // [256][64]
    float* Ms = sh + 2 * SEQ * HDIM; // [256]

    int bh = blockIdx.x;
    int b = bh / NHEAD;
    int h = bh % NHEAD;
    int t = threadIdx.x;   // query row within sequence

    const float* base = qkv + (size_t)b * SEQ * (3 * HID);

    // stage K, V, mask bias
    {
        const float* krow = base + (size_t)t * (3 * HID) + HID + h * HDIM;
        const float* vrow = base + (size_t)t * (3 * HID) + 2 * HID + h * HDIM;
        #pragma unroll
        for (int d = 0; d < HDIM; d += 4) {
            *reinterpret_cast<float4*>(&Ks[t * HDIM + d]) =
                *reinterpret_cast<const float4*>(krow + d);
            *reinterpret_cast<float4*>(&Vs[t * HDIM + d]) =
                *reinterpret_cast<const float4*>(vrow + d);
        }
        Ms[t] = (1.0f - (float)amask[b * SEQ + t]) * -1e9f;
    }
    __syncthreads();

    // load this thread's query row
    float q[HDIM];
    {
        const float* qrow = base + (size_t)t * (3 * HID) + h * HDIM;
        #pragma unroll
        for (int d = 0; d < HDIM; d++) q[d] = qrow[d];
    }

    // pass 1: scores + max
    float sc[SEQ];
    float m = -1e30f;
    #pragma unroll 1
    for (int k = 0; k < SEQ; k++) {
        float s = 0.f;
        #pragma unroll
        for (int d = 0; d < HDIM; d++) s += q[d] * Ks[k * HDIM + d];
        s = s * 0.125f + Ms[k];
        sc[k] = s;
        m = fmaxf(m, s);
    }

    // pass 2: exp + weighted sum of V
    float l = 0.f;
    float accv[HDIM];
    #pragma unroll
    for (int d = 0; d < HDIM; d++) accv[d] = 0.f;
    #pragma unroll 1
    for (int k = 0; k < SEQ; k++) {
        float p = __expf(sc[k] - m);
        l += p;
        #pragma unroll
        for (int d = 0; d < HDIM; d++) accv[d] += p * Vs[k * HDIM + d];
    }
    float inv = 1.0f / l;
    float* orow = out + (size_t)(b * SEQ + t) * HID + h * HDIM;
    #pragma unroll
    for (int d = 0; d < HDIM; d++) orow[d] = accv[d] * inv;
}

// ---------------------------------------------------------------------------
// Classifier: logits[row, 0..8] = x[row] @ Wcls + bcls  -> out (d_out+1)
// ---------------------------------------------------------------------------
__global__ __launch_bounds__(256) void cls_kernel(
    const float* __restrict__ x, const float* __restrict__ W,
    const float* __restrict__ bias, float* __restrict__ out)
{
    __shared__ float red[256];
    int row = blockIdx.x;
    int t = threadIdx.x;
    float part[NTAGS];
    #pragma unroll
    for (int n = 0; n < NTAGS; n++) part[n] = 0.f;
    for (int k = t; k < HID; k += 256) {
        float xv = x[(size_t)row * HID + k];
        #pragma unroll
        for (int n = 0; n < NTAGS; n++) part[n] += xv * W[k * NTAGS + n];
    }
    #pragma unroll
    for (int n = 0; n < NTAGS; n++) {
        float s = block_reduce_sum(part[n], red);
        if (t == 0) out[(size_t)row * NTAGS + n] = s + bias[n];
    }
}

// ---------------------------------------------------------------------------
// CRF: one warp per batch element. Lanes 0..8 carry the forward scores.
// ---------------------------------------------------------------------------
__global__ __launch_bounds__(32) void crf_kernel(
    const float* __restrict__ logits, const int* __restrict__ labels,
    const float* __restrict__ cstart, const float* __restrict__ cend,
    const float* __restrict__ ctrans, float* __restrict__ nmd)
{
    int b = blockIdx.x;
    int lane = threadIdx.x;
    const float* lg = logits + (size_t)b * SEQ * NTAGS;
    const int* lab = labels + b * SEQ;

    // --- numerator (parallel over s) ---
    float part = 0.f;
    int cnt = 0;
    for (int s = lane; s < SEQ; s += 32) {
        int lv = lab[s];
        bool mk = (s == 0) || (lv != -100);
        cnt += mk ? 1 : 0;
        if (s >= 1 && mk) {
            int lp = lab[s - 1]; int tp = (lp == -100) ? 0 : lp;
            int tc = (lv == -100) ? 0 : lv;
            part += ctrans[tp * NTAGS + tc] + lg[s * NTAGS + tc];
        }
    }
    #pragma unroll
    for (int o = 16; o > 0; o >>= 1) {
        part += __shfl_xor_sync(0xffffffffu, part, o);
        cnt  += __shfl_xor_sync(0xffffffffu, cnt, o);
    }

    // --- forward algorithm: lane t owns score[t] ---
    int t = (lane < NTAGS) ? lane : 0;
    float tt[NTAGS];
    #pragma unroll
    for (int i = 0; i < NTAGS; i++) tt[i] = ctrans[i * NTAGS + t];
    float score = cstart[t] + lg[t];

    for (int s = 1; s < SEQ; s++) {
        float e = lg[s * NTAGS + t];
        float v[NTAGS];
        float vmax = -1e30f;
        #pragma unroll
        for (int i = 0; i < NTAGS; i++) {
            float si = __shfl_sync(0xffffffffu, score, i);
            v[i] = si + tt[i];
            vmax = fmaxf(vmax, v[i]);
        }
        float sm = 0.f;
        #pragma unroll
        for (int i = 0; i < NTAGS; i++) sm += __expf(v[i] - vmax);
        float nxt = vmax + __logf(sm) + e;
        int lv = lab[s];
        bool mk = (lv != -100);
        score = mk ? nxt : score;
    }

    float fin = score + cend[t];
    float gmax = -1e30f;
    #pragma unroll
    for (int i = 0; i < NTAGS; i++)
        gmax = fmaxf(gmax, __shfl_sync(0xffffffffu, fin, i));
    float gs = 0.f;
    #pragma unroll
    for (int i = 0; i < NTAGS; i++)
        gs += __expf(__shfl_sync(0xffffffffu, fin, i) - gmax);
    float denom = gmax + __logf(gs);

    if (lane == 0) {
        int l0 = lab[0]; int t0 = (l0 == -100) ? 0 : l0;
        int seq_end = cnt - 1;
        int le = lab[seq_end]; int te = (le == -100) ? 0 : le;
        float num = part + cstart[t0] + lg[t0] + cend[te];
        nmd[b] = num - denom;
    }
}

__global__ __launch_bounds__(32) void loss_kernel(
    const float* __restrict__ nmd, float* __restrict__ out)
{
    int lane = threadIdx.x;
    float v = (lane < BATCH) ? nmd[lane] : 0.f;
    #pragma unroll
    for (int o = 16; o > 0; o >>= 1) v += __shfl_xor_sync(0xffffffffu, v, o);
    if (lane == 0) out[0] = -(v * (1.0f / BATCH));
}

// ---------------------------------------------------------------------------
// Launcher
// ---------------------------------------------------------------------------
extern "C" void kernel_launch(void* const* d_in, const int* in_sizes, int n_in,
                              void* d_out, int out_size)
{
    const int*   input_ids = (const int*)d_in[0];
    const int*   amask     = (const int*)d_in[1];
    const int*   labels    = (const int*)d_in[2];
    const float* word_emb  = (const float*)d_in[3];
    const float* pos_emb   = (const float*)d_in[4];
    const float* eln_s     = (const float*)d_in[5];
    const float* eln_b     = (const float*)d_in[6];
    const float* Wqkv      = (const float*)d_in[7];
    const float* bqkv      = (const float*)d_in[8];
    const float* Wo        = (const float*)d_in[9];
    const float* bo        = (const float*)d_in[10];
    const float* ln1s      = (const float*)d_in[11];
    const float* ln1b      = (const float*)d_in[12];
    const float* Wff1      = (const float*)d_in[13];
    const float* bff1      = (const float*)d_in[14];
    const float* Wff2      = (const float*)d_in[15];
    const float* bff2      = (const float*)d_in[16];
    const float* ln2s      = (const float*)d_in[17];
    const float* ln2b      = (const float*)d_in[18];
    const float* Wcls      = (const float*)d_in[19];
    const float* bcls      = (const float*)d_in[20];
    const float* cstart    = (const float*)d_in[21];
    const float* cend      = (const float*)d_in[22];
    const float* ctrans    = (const float*)d_in[23];
    float* out = (float*)d_out;

    float *x, *qkv, *attn, *ffn, *tmp, *nmd;
    cudaGetSymbolAddress((void**)&x,    g_x);
    cudaGetSymbolAddress((void**)&qkv,  g_qkv);
    cudaGetSymbolAddress((void**)&attn, g_attn);
    cudaGetSymbolAddress((void**)&ffn,  g_ffn);
    cudaGetSymbolAddress((void**)&tmp,  g_tmp);
    cudaGetSymbolAddress((void**)&nmd,  g_nmd);

    cudaFuncSetAttribute(attn_kernel,
        cudaFuncAttributeMaxDynamicSharedMemorySize, ATTN_SMEM);

    embed_ln_kernel<<<NTOK, 256>>>(input_ids, word_emb, pos_emb, eln_s, eln_b, x);

    for (int L = 0; L < NLAYER; L++) {
        sgemm_kernel<<<dim3(3 * HID / BN, NTOK / BM), 256>>>(
            x, Wqkv + (size_t)L * HID * 3 * HID, bqkv + (size_t)L * 3 * HID,
            qkv, NTOK, 3 * HID, HID, 0);

        attn_kernel<<<BATCH * NHEAD, 256, ATTN_SMEM>>>(qkv, amask, attn);

        sgemm_kernel<<<dim3(HID / BN, NTOK / BM), 256>>>(
            attn, Wo + (size_t)L * HID * HID, bo + (size_t)L * HID,
            tmp, NTOK, HID, HID, 0);

        resid_ln_kernel<<<NTOK, 256>>>(x, tmp, ln1s + (size_t)L * HID, ln1b + (size_t)L * HID);

        sgemm_kernel<<<dim3(FFN / BN, NTOK / BM), 256>>>(
            x, Wff1 + (size_t)L * HID * FFN, bff1 + (size_t)L * FFN,
            ffn, NTOK, FFN, HID, 1);

        sgemm_kernel<<<dim3(HID / BN, NTOK / BM), 256>>>(
            ffn, Wff2 + (size_t)L * FFN * HID, bff2 + (size_t)L * HID,
            tmp, NTOK, HID, FFN, 0);

        resid_ln_kernel<<<NTOK, 256>>>(x, tmp, ln2s + (size_t)L * HID, ln2b + (size_t)L * HID);
    }

    cls_kernel<<<NTOK, 256>>>(x, Wcls, bcls, out + 1);
    crf_kernel<<<BATCH, 32>>>(out + 1, labels, cstart, cend, ctrans, nmd);
    loss_kernel<<<1, 32>>>(nmd, out);
}

// round 3
// speedup vs baseline: 1.7478x; 1.7478x over previous
#include <cuda_runtime.h>
#include <cuda_bf16.h>
#include <math.h>
#include <stdint.h>

// ---------------------------------------------------------------------------
// Problem constants
// ---------------------------------------------------------------------------
#define BATCH 16
#define SEQ 256
#define NTOK (BATCH * SEQ)          // 4096
#define HID 768
#define NHEAD 12
#define HDIM 64
#define FFN 3072
#define NLAYER 6
#define NTAGS 9

// ---------------------------------------------------------------------------
// Scratch (device globals; no allocation allowed)
// ---------------------------------------------------------------------------
__device__ float g_x[NTOK * HID];
__device__ float g_qkv[NTOK * 3 * HID];
__device__ float g_attn[NTOK * HID];
__device__ float g_ffn[NTOK * FFN];
__device__ float g_tmp[NTOK * HID];
__device__ float g_nmd[BATCH];

// ---------------------------------------------------------------------------
// helpers
// ---------------------------------------------------------------------------
__device__ __forceinline__ uint32_t f2tf32(float x) {
    uint32_t r;
    asm("cvt.rna.tf32.f32 %0, %1;" : "=r"(r) : "f"(x));
    return r;
}

__device__ __forceinline__ void mma_tf32_16x8x8(
    float& c0, float& c1, float& c2, float& c3,
    uint32_t a0, uint32_t a1, uint32_t a2, uint32_t a3,
    uint32_t b0, uint32_t b1)
{
    asm volatile(
        "mma.sync.aligned.m16n8k8.row.col.f32.tf32.tf32.f32 "
        "{%0,%1,%2,%3}, {%4,%5,%6,%7}, {%8,%9}, {%0,%1,%2,%3};"
        : "+f"(c0), "+f"(c1), "+f"(c2), "+f"(c3)
        : "r"(a0), "r"(a1), "r"(a2), "r"(a3), "r"(b0), "r"(b1));
}

__device__ __forceinline__ float gelu_tanh(float v) {
    float c = 0.7978845608028654f;
    float u = c * (v + 0.044715f * v * v * v);
    return 0.5f * v * (1.0f + tanhf(u));
}

// ---------------------------------------------------------------------------
// tf32 tensor-core GEMM: C[M,N] = A[M,K] @ B[K,N] + bias   (act=1 -> gelu)
// CTA tile 128x128, BK=32, 256 threads (8 warps, 2m x 4n), warp tile 64x32.
// Requires M%128==0, N%128==0, K%32==0.
// ---------------------------------------------------------------------------
#define ASTRIDE 36
#define BSTRIDE 132

__global__ __launch_bounds__(256) void gemm_tc_kernel(
    const float* __restrict__ A, const float* __restrict__ B,
    const float* __restrict__ bias, float* __restrict__ C,
    int M, int N, int K, int act)
{
    __shared__ uint32_t As[128][ASTRIDE];   // [m][k]  (tf32 bits)
    __shared__ uint32_t Bs[32][BSTRIDE];    // [k][n]  (tf32 bits)

    const int tid = threadIdx.x;
    const int wid = tid >> 5;
    const int lane = tid & 31;
    const int gid = lane >> 2;      // 0..7
    const int tig = lane & 3;       // 0..3
    const int warp_m = wid >> 2;    // 0..1
    const int warp_n = wid & 3;     // 0..3
    const int moff = warp_m * 64;
    const int noff = warp_n * 32;

    const int m0 = blockIdx.y * 128;
    const int n0 = blockIdx.x * 128;

    // global->reg staging indices
    const int arow = tid >> 1;            // 0..127
    const int acol = (tid & 1) * 16;      // 0 or 16 (floats)
    const int brow = tid >> 3;            // 0..31
    const int bcol = (tid & 7) * 16;      // 0..112 (floats)

    float4 pa[4], pb[4];

    float acc[4][4][4];
    #pragma unroll
    for (int i = 0; i < 4; i++)
        #pragma unroll
        for (int j = 0; j < 4; j++)
            #pragma unroll
            for (int q = 0; q < 4; q++) acc[i][j][q] = 0.f;

    const int nch = K >> 5;

    // prologue: load chunk 0
    #pragma unroll
    for (int i = 0; i < 4; i++) {
        pa[i] = *reinterpret_cast<const float4*>(
            A + (size_t)(m0 + arow) * K + acol + i * 4);
        pb[i] = *reinterpret_cast<const float4*>(
            B + (size_t)brow * N + n0 + bcol + i * 4);
    }
    #pragma unroll
    for (int i = 0; i < 4; i++) {
        *reinterpret_cast<uint4*>(&As[arow][acol + i * 4]) =
            make_uint4(f2tf32(pa[i].x), f2tf32(pa[i].y), f2tf32(pa[i].z), f2tf32(pa[i].w));
        *reinterpret_cast<uint4*>(&Bs[brow][bcol + i * 4]) =
            make_uint4(f2tf32(pb[i].x), f2tf32(pb[i].y), f2tf32(pb[i].z), f2tf32(pb[i].w));
    }
    __syncthreads();

    #pragma unroll 1
    for (int c = 0; c < nch; c++) {
        // prefetch next chunk into registers
        if (c + 1 < nch) {
            int kc = (c + 1) * 32;
            #pragma unroll
            for (int i = 0; i < 4; i++) {
                pa[i] = *reinterpret_cast<const float4*>(
                    A + (size_t)(m0 + arow) * K + kc + acol + i * 4);
                pb[i] = *reinterpret_cast<const float4*>(
                    B + (size_t)(kc + brow) * N + n0 + bcol + i * 4);
            }
        }

        // compute 4 k-steps of 8
        #pragma unroll
        for (int ks = 0; ks < 4; ks++) {
            int k0 = ks * 8;
            uint32_t a[4][4];
            #pragma unroll
            for (int mf = 0; mf < 4; mf++) {
                int r = moff + mf * 16 + gid;
                a[mf][0] = As[r][k0 + tig];
                a[mf][1] = As[r + 8][k0 + tig];
                a[mf][2] = As[r][k0 + tig + 4];
                a[mf][3] = As[r + 8][k0 + tig + 4];
            }
            uint32_t b[4][2];
            #pragma unroll
            for (int nf = 0; nf < 4; nf++) {
                int nc = noff + nf * 8 + gid;
                b[nf][0] = Bs[k0 + tig][nc];
                b[nf][1] = Bs[k0 + tig + 4][nc];
            }
            #pragma unroll
            for (int mf = 0; mf < 4; mf++)
                #pragma unroll
                for (int nf = 0; nf < 4; nf++)
                    mma_tf32_16x8x8(acc[mf][nf][0], acc[mf][nf][1],
                                    acc[mf][nf][2], acc[mf][nf][3],
                                    a[mf][0], a[mf][1], a[mf][2], a[mf][3],
                                    b[nf][0], b[nf][1]);
        }

        __syncthreads();
        if (c + 1 < nch) {
            #pragma unroll
            for (int i = 0; i < 4; i++) {
                *reinterpret_cast<uint4*>(&As[arow][acol + i * 4]) =
                    make_uint4(f2tf32(pa[i].x), f2tf32(pa[i].y),
                               f2tf32(pa[i].z), f2tf32(pa[i].w));
                *reinterpret_cast<uint4*>(&Bs[brow][bcol + i * 4]) =
                    make_uint4(f2tf32(pb[i].x), f2tf32(pb[i].y),
                               f2tf32(pb[i].z), f2tf32(pb[i].w));
            }
            __syncthreads();
        }
    }

    // epilogue
    #pragma unroll
    for (int mf = 0; mf < 4; mf++) {
        #pragma unroll
        for (int half = 0; half < 2; half++) {
            int row = m0 + moff + mf * 16 + gid + half * 8;
            float* crow = C + (size_t)row * N + n0 + noff;
            const float* brow_ = bias + n0 + noff;
            #pragma unroll
            for (int nf = 0; nf < 4; nf++) {
                int cl = nf * 8 + 2 * tig;
                float2 v;
                v.x = acc[mf][nf][half * 2 + 0] + brow_[cl];
                v.y = acc[mf][nf][half * 2 + 1] + brow_[cl + 1];
                if (act == 1) { v.x = gelu_tanh(v.x); v.y = gelu_tanh(v.y); }
                *reinterpret_cast<float2*>(crow + cl) = v;
            }
        }
    }
}

// ---------------------------------------------------------------------------
// Block reduction helper (blockDim.x == 256)
// ---------------------------------------------------------------------------
__device__ __forceinline__ float block_reduce_sum(float v, float* red) {
    int t = threadIdx.x;
    red[t] = v;
    __syncthreads();
    #pragma unroll
    for (int s = 128; s > 0; s >>= 1) {
        if (t < s) red[t] += red[t + s];
        __syncthreads();
    }
    float r = red[0];
    __syncthreads();
    return r;
}

// ---------------------------------------------------------------------------
// Embedding + LayerNorm
// ---------------------------------------------------------------------------
__global__ __launch_bounds__(256) void embed_ln_kernel(
    const int* __restrict__ ids, const float* __restrict__ wemb,
    const float* __restrict__ pemb, const float* __restrict__ lns,
    const float* __restrict__ lnb, float* __restrict__ xout)
{
    __shared__ float red[256];
    int row = blockIdx.x;
    int spos = row & (SEQ - 1);
    int id = ids[row];
    int t = threadIdx.x;

    float v[3];
    #pragma unroll
    for (int i = 0; i < 3; i++) {
        int c = t + i * 256;
        v[i] = wemb[(size_t)id * HID + c] + pemb[(size_t)spos * HID + c];
    }
    float mean = block_reduce_sum(v[0] + v[1] + v[2], red) * (1.0f / HID);
    float sq = 0.f;
    #pragma unroll
    for (int i = 0; i < 3; i++) { float d = v[i] - mean; sq += d * d; }
    float inv = rsqrtf(block_reduce_sum(sq, red) * (1.0f / HID) + 1e-12f);
    #pragma unroll
    for (int i = 0; i < 3; i++) {
        int c = t + i * 256;
        xout[(size_t)row * HID + c] = (v[i] - mean) * inv * lns[c] + lnb[c];
    }
}

// ---------------------------------------------------------------------------
// Residual + LayerNorm
// ---------------------------------------------------------------------------
__global__ __launch_bounds__(256) void resid_ln_kernel(
    float* __restrict__ x, const float* __restrict__ y,
    const float* __restrict__ lns, const float* __restrict__ lnb)
{
    __shared__ float red[256];
    int row = blockIdx.x;
    int t = threadIdx.x;
    float v[3];
    #pragma unroll
    for (int i = 0; i < 3; i++) {
        int c = t + i * 256;
        v[i] = x[(size_t)row * HID + c] + y[(size_t)row * HID + c];
    }
    float mean = block_reduce_sum(v[0] + v[1] + v[2], red) * (1.0f / HID);
    float sq = 0.f;
    #pragma unroll
    for (int i = 0; i < 3; i++) { float d = v[i] - mean; sq += d * d; }
    float inv = rsqrtf(block_reduce_sum(sq, red) * (1.0f / HID) + 1e-12f);
    #pragma unroll
    for (int i = 0; i < 3; i++) {
        int c = t + i * 256;
        x[(size_t)row * HID + c] = (v[i] - mean) * inv * lns[c] + lnb[c];
    }
}

// ---------------------------------------------------------------------------
// Fused attention, online softmax. One block per (b,h), thread = query row.
// ---------------------------------------------------------------------------
#define ATTN_SMEM (2 * SEQ * HDIM * 4 + SEQ * 4)

__global__ __launch_bounds__(256) void attn_kernel(
    const float* __restrict__ qkv, const int* __restrict__ amask,
    float* __restrict__ out)
{
    extern __shared__ float sh[];
    float* Ks = sh;
    float* Vs = sh + SEQ * HDIM;
    float* Ms = sh + 2 * SEQ * HDIM;

    int bh = blockIdx.x;
    int b = bh / NHEAD;
    int h = bh % NHEAD;
    int t = threadIdx.x;

    const float* base = qkv + (size_t)b * SEQ * (3 * HID);

    {
        const float* krow = base + (size_t)t * (3 * HID) + HID + h * HDIM;
        const float* vrow = base + (size_t)t * (3 * HID) + 2 * HID + h * HDIM;
        #pragma unroll
        for (int d = 0; d < HDIM; d += 4) {
            *reinterpret_cast<float4*>(&Ks[t * HDIM + d]) =
                *reinterpret_cast<const float4*>(krow + d);
            *reinterpret_cast<float4*>(&Vs[t * HDIM + d]) =
                *reinterpret_cast<const float4*>(vrow + d);
        }
        Ms[t] = (1.0f - (float)amask[b * SEQ + t]) * -1e9f;
    }
    __syncthreads();

    float q[HDIM];
    {
        const float* qrow = base + (size_t)t * (3 * HID) + h * HDIM;
        #pragma unroll
        for (int d = 0; d < HDIM; d++) q[d] = qrow[d];
    }

    float m = -1e30f, l = 0.f;
    float accv[HDIM];
    #pragma unroll
    for (int d = 0; d < HDIM; d++) accv[d] = 0.f;

    #pragma unroll 1
    for (int k = 0; k < SEQ; k++) {
        float s = 0.f;
        #pragma unroll
        for (int d = 0; d < HDIM; d++) s += q[d] * Ks[k * HDIM + d];
        s = s * 0.125f + Ms[k];
        if (s <= m) {
            float p = __expf(s - m);
            l += p;
            #pragma unroll
            for (int d = 0; d < HDIM; d++) accv[d] += p * Vs[k * HDIM + d];
        } else {
            float corr = __expf(m - s);
            l = l * corr + 1.f;
            #pragma unroll
            for (int d = 0; d < HDIM; d++)
                accv[d] = accv[d] * corr + Vs[k * HDIM + d];
            m = s;
        }
    }
    float inv = 1.0f / l;
    float* orow = out + (size_t)(b * SEQ + t) * HID + h * HDIM;
    #pragma unroll
    for (int d = 0; d < HDIM; d++) orow[d] = accv[d] * inv;
}

// ---------------------------------------------------------------------------
// Classifier: logits = x @ Wcls + bcls
// ---------------------------------------------------------------------------
__global__ __launch_bounds__(256) void cls_kernel(
    const float* __restrict__ x, const float* __restrict__ W,
    const float* __restrict__ bias, float* __restrict__ out)
{
    __shared__ float red[256];
    int row = blockIdx.x;
    int t = threadIdx.x;
    float part[NTAGS];
    #pragma unroll
    for (int n = 0; n < NTAGS; n++) part[n] = 0.f;
    for (int k = t; k < HID; k += 256) {
        float xv = x[(size_t)row * HID + k];
        #pragma unroll
        for (int n = 0; n < NTAGS; n++) part[n] += xv * W[k * NTAGS + n];
    }
    #pragma unroll
    for (int n = 0; n < NTAGS; n++) {
        float s = block_reduce_sum(part[n], red);
        if (t == 0) out[(size_t)row * NTAGS + n] = s + bias[n];
    }
}

// ---------------------------------------------------------------------------
// CRF: one warp per batch element
// ---------------------------------------------------------------------------
__global__ __launch_bounds__(32) void crf_kernel(
    const float* __restrict__ logits, const int* __restrict__ labels,
    const float* __restrict__ cstart, const float* __restrict__ cend,
    const float* __restrict__ ctrans, float* __restrict__ nmd)
{
    int b = blockIdx.x;
    int lane = threadIdx.x;
    const float* lg = logits + (size_t)b * SEQ * NTAGS;
    const int* lab = labels + b * SEQ;

    float part = 0.f;
    int cnt = 0;
    for (int s = lane; s < SEQ; s += 32) {
        int lv = lab[s];
        bool mk = (s == 0) || (lv != -100);
        cnt += mk ? 1 : 0;
        if (s >= 1 && mk) {
            int lp = lab[s - 1]; int tp = (lp == -100) ? 0 : lp;
            int tc = (lv == -100) ? 0 : lv;
            part += ctrans[tp * NTAGS + tc] + lg[s * NTAGS + tc];
        }
    }
    #pragma unroll
    for (int o = 16; o > 0; o >>= 1) {
        part += __shfl_xor_sync(0xffffffffu, part, o);
        cnt  += __shfl_xor_sync(0xffffffffu, cnt, o);
    }

    int t = (lane < NTAGS) ? lane : 0;
    float tt[NTAGS];
    #pragma unroll
    for (int i = 0; i < NTAGS; i++) tt[i] = ctrans[i * NTAGS + t];
    float score = cstart[t] + lg[t];

    for (int s = 1; s < SEQ; s++) {
        float e = lg[s * NTAGS + t];
        float v[NTAGS];
        float vmax = -1e30f;
        #pragma unroll
        for (int i = 0; i < NTAGS; i++) {
            float si = __shfl_sync(0xffffffffu, score, i);
            v[i] = si + tt[i];
            vmax = fmaxf(vmax, v[i]);
        }
        float smv = 0.f;
        #pragma unroll
        for (int i = 0; i < NTAGS; i++) smv += __expf(v[i] - vmax);
        float nxt = vmax + __logf(smv) + e;
        bool mk = (lab[s] != -100);
        score = mk ? nxt : score;
    }

    float fin = score + cend[t];
    float gmax = -1e30f;
    #pragma unroll
    for (int i = 0; i < NTAGS; i++)
        gmax = fmaxf(gmax, __shfl_sync(0xffffffffu, fin, i));
    float gs = 0.f;
    #pragma unroll
    for (int i = 0; i < NTAGS; i++)
        gs += __expf(__shfl_sync(0xffffffffu, fin, i) - gmax);
    float denom = gmax + __logf(gs);

    if (lane == 0) {
        int l0 = lab[0]; int t0 = (l0 == -100) ? 0 : l0;
        int seq_end = cnt - 1;
        int le = lab[seq_end]; int te = (le == -100) ? 0 : le;
        float num = part + cstart[t0] + lg[t0] + cend[te];
        nmd[b] = num - denom;
    }
}

__global__ __launch_bounds__(32) void loss_kernel(
    const float* __restrict__ nmd, float* __restrict__ out)
{
    int lane = threadIdx.x;
    float v = (lane < BATCH) ? nmd[lane] : 0.f;
    #pragma unroll
    for (int o = 16; o > 0; o >>= 1) v += __shfl_xor_sync(0xffffffffu, v, o);
    if (lane == 0) out[0] = -(v * (1.0f / BATCH));
}

// ---------------------------------------------------------------------------
// Launcher
// ---------------------------------------------------------------------------
extern "C" void kernel_launch(void* const* d_in, const int* in_sizes, int n_in,
                              void* d_out, int out_size)
{
    const int*   input_ids = (const int*)d_in[0];
    const int*   amask     = (const int*)d_in[1];
    const int*   labels    = (const int*)d_in[2];
    const float* word_emb  = (const float*)d_in[3];
    const float* pos_emb   = (const float*)d_in[4];
    const float* eln_s     = (const float*)d_in[5];
    const float* eln_b     = (const float*)d_in[6];
    const float* Wqkv      = (const float*)d_in[7];
    const float* bqkv      = (const float*)d_in[8];
    const float* Wo        = (const float*)d_in[9];
    const float* bo        = (const float*)d_in[10];
    const float* ln1s      = (const float*)d_in[11];
    const float* ln1b      = (const float*)d_in[12];
    const float* Wff1      = (const float*)d_in[13];
    const float* bff1      = (const float*)d_in[14];
    const float* Wff2      = (const float*)d_in[15];
    const float* bff2      = (const float*)d_in[16];
    const float* ln2s      = (const float*)d_in[17];
    const float* ln2b      = (const float*)d_in[18];
    const float* Wcls      = (const float*)d_in[19];
    const float* bcls      = (const float*)d_in[20];
    const float* cstart    = (const float*)d_in[21];
    const float* cend      = (const float*)d_in[22];
    const float* ctrans    = (const float*)d_in[23];
    float* out = (float*)d_out;

    float *x, *qkv, *attn, *ffn, *tmp, *nmd;
    cudaGetSymbolAddress((void**)&x,    g_x);
    cudaGetSymbolAddress((void**)&qkv,  g_qkv);
    cudaGetSymbolAddress((void**)&attn, g_attn);
    cudaGetSymbolAddress((void**)&ffn,  g_ffn);
    cudaGetSymbolAddress((void**)&tmp,  g_tmp);
    cudaGetSymbolAddress((void**)&nmd,  g_nmd);

    cudaFuncSetAttribute(attn_kernel,
        cudaFuncAttributeMaxDynamicSharedMemorySize, ATTN_SMEM);

    embed_ln_kernel<<<NTOK, 256>>>(input_ids, word_emb, pos_emb, eln_s, eln_b, x);

    for (int L = 0; L < NLAYER; L++) {
        gemm_tc_kernel<<<dim3(3 * HID / 128, NTOK / 128), 256>>>(
            x, Wqkv + (size_t)L * HID * 3 * HID, bqkv + (size_t)L * 3 * HID,
            qkv, NTOK, 3 * HID, HID, 0);

        attn_kernel<<<BATCH * NHEAD, 256, ATTN_SMEM>>>(qkv, amask, attn);

        gemm_tc_kernel<<<dim3(HID / 128, NTOK / 128), 256>>>(
            attn, Wo + (size_t)L * HID * HID, bo + (size_t)L * HID,
            tmp, NTOK, HID, HID, 0);

        resid_ln_kernel<<<NTOK, 256>>>(x, tmp, ln1s + (size_t)L * HID, ln1b + (size_t)L * HID);

        gemm_tc_kernel<<<dim3(FFN / 128, NTOK / 128), 256>>>(
            x, Wff1 + (size_t)L * HID * FFN, bff1 + (size_t)L * FFN,
            ffn, NTOK, FFN, HID, 1);

        gemm_tc_kernel<<<dim3(HID / 128, NTOK / 128), 256>>>(
            ffn, Wff2 + (size_t)L * FFN * HID, bff2 + (size_t)L * HID,
            tmp, NTOK, HID, FFN, 0);

        resid_ln_kernel<<<NTOK, 256>>>(x, tmp, ln2s + (size_t)L * HID, ln2b + (size_t)L * HID);
    }

    cls_kernel<<<NTOK, 256>>>(x, Wcls, bcls, out + 1);
    crf_kernel<<<BATCH, 32>>>(out + 1, labels, cstart, cend, ctrans, nmd);
    loss_kernel<<<1, 32>>>(nmd, out);
}

// round 5
// speedup vs baseline: 3.7821x; 2.1639x over previous
#include <cuda_runtime.h>
#include <cuda_bf16.h>
#include <math.h>
#include <stdint.h>

// ---------------------------------------------------------------------------
// Problem constants
// ---------------------------------------------------------------------------
#define BATCH 16
#define SEQ 256
#define NTOK (BATCH * SEQ)          // 4096
#define HID 768
#define NHEAD 12
#define HDIM 64
#define FFN 3072
#define NLAYER 6
#define NTAGS 9

// ---------------------------------------------------------------------------
// Scratch (device globals; no allocation allowed)
// ---------------------------------------------------------------------------
__device__ float g_x[NTOK * HID];
__device__ float g_qkv[NTOK * 3 * HID];
__device__ float g_attn[NTOK * HID];
__device__ float g_ffn[NTOK * FFN];
__device__ float g_tmp[NTOK * HID];
__device__ float g_nmd[BATCH];

// ---------------------------------------------------------------------------
// helpers
// ---------------------------------------------------------------------------
__device__ __forceinline__ uint32_t smem_u32(const void* p) {
    uint32_t a;
    asm("{ .reg .u64 t; cvta.to.shared.u64 t, %1; cvt.u32.u64 %0, t; }"
        : "=r"(a) : "l"(p));
    return a;
}

__device__ __forceinline__ uint32_t f2tf32(float x) {
    uint32_t r;
    asm("cvt.rna.tf32.f32 %0, %1;" : "=r"(r) : "f"(x));
    return r;
}

__device__ __forceinline__ void mma_tf32_16x8x8(
    float* c, uint32_t a0, uint32_t a1, uint32_t a2, uint32_t a3,
    uint32_t b0, uint32_t b1)
{
    asm volatile(
        "mma.sync.aligned.m16n8k8.row.col.f32.tf32.tf32.f32 "
        "{%0,%1,%2,%3}, {%4,%5,%6,%7}, {%8,%9}, {%0,%1,%2,%3};"
        : "+f"(c[0]), "+f"(c[1]), "+f"(c[2]), "+f"(c[3])
        : "r"(a0), "r"(a1), "r"(a2), "r"(a3), "r"(b0), "r"(b1));
}

__device__ __forceinline__ float gelu_tanh(float v) {
    float c = 0.7978845608028654f;
    float u = c * (v + 0.044715f * v * v * v);
    return 0.5f * v * (1.0f + tanhf(u));
}

#define CP_ASYNC16(dst, src) \
    asm volatile("cp.async.cg.shared.global [%0], [%1], 16;" \
        :: "r"(dst), "l"(src) : "memory")
#define CP_COMMIT() asm volatile("cp.async.commit_group;" ::: "memory")
#define CP_WAIT2()  asm volatile("cp.async.wait_group 2;" ::: "memory")

// ---------------------------------------------------------------------------
// tf32 tensor-core GEMM with cp.async 3-stage pipeline.
// C[M,N] = A[M,K] @ B[K,N] + bias   (act=1 -> gelu)
// CTA tile 128x128, BK=32, 256 threads (8 warps 2m x 4n), warp tile 64x32.
// ---------------------------------------------------------------------------
#define AST 36
#define BST 136
#define A_STAGE (128 * AST)
#define B_STAGE (32 * BST)
#define GEMM_DSMEM ((3 * A_STAGE + 3 * B_STAGE) * 4)

__global__ __launch_bounds__(256) void gemm_tc_kernel(
    const float* __restrict__ A, const float* __restrict__ B,
    const float* __restrict__ bias, float* __restrict__ C,
    int M, int N, int K, int act)
{
    extern __shared__ float gsm[];
    float* AsB = gsm;                 // [3][128][AST]
    float* BsB = gsm + 3 * A_STAGE;   // [3][32][BST]
    const uint32_t s_as = smem_u32(AsB);
    const uint32_t s_bs = smem_u32(BsB);

    const int tid = threadIdx.x;
    const int wid = tid >> 5;
    const int lane = tid & 31;
    const int gid = lane >> 2;
    const int tig = lane & 3;
    const int moff = (wid >> 2) * 64;
    const int noff = (wid & 3) * 32;

    const int m0 = blockIdx.y * 128;
    const int n0 = blockIdx.x * 128;

    const int ar = tid >> 3, ac = (tid & 7) * 4;     // A: 4 rows of 32-col tile
    const int br = tid >> 5, bc = (tid & 31) * 4;    // B: 4 rows of 128-col tile

    float acc[4][4][4];
    #pragma unroll
    for (int i = 0; i < 4; i++)
        #pragma unroll
        for (int j = 0; j < 4; j++)
            #pragma unroll
            for (int q = 0; q < 4; q++) acc[i][j][q] = 0.f;

    const int nch = K >> 5;

    auto issue = [&](int stage, int kc) {
        #pragma unroll
        for (int i = 0; i < 4; i++) {
            int r = i * 32 + ar;
            uint32_t d = s_as + (uint32_t)(stage * A_STAGE + r * AST + ac) * 4u;
            const float* s = A + (size_t)(m0 + r) * K + kc + ac;
            CP_ASYNC16(d, s);
        }
        #pragma unroll
        for (int i = 0; i < 4; i++) {
            int r = i * 8 + br;
            uint32_t d = s_bs + (uint32_t)(stage * B_STAGE + r * BST + bc) * 4u;
            const float* s = B + (size_t)(kc + r) * N + n0 + bc;
            CP_ASYNC16(d, s);
        }
        CP_COMMIT();
    };

    issue(0, 0);
    issue(1, 32);

    #pragma unroll 1
    for (int c = 0; c < nch; c++) {
        if (c + 2 < nch) issue((c + 2) % 3, (c + 2) * 32);
        else CP_COMMIT();
        CP_WAIT2();
        __syncthreads();

        const float* Asb = AsB + (c % 3) * A_STAGE;
        const float* Bsb = BsB + (c % 3) * B_STAGE;

        #pragma unroll
        for (int ks = 0; ks < 4; ks++) {
            int k0 = ks * 8;
            uint32_t a[2][4];
            #pragma unroll
            for (int mf = 0; mf < 2; mf++) {
                int r = moff + mf * 16 + gid;
                a[mf][0] = f2tf32(Asb[r * AST + k0 + tig]);
                a[mf][1] = f2tf32(Asb[(r + 8) * AST + k0 + tig]);
                a[mf][2] = f2tf32(Asb[r * AST + k0 + tig + 4]);
                a[mf][3] = f2tf32(Asb[(r + 8) * AST + k0 + tig + 4]);
            }
            uint32_t a2[2][4];
            #pragma unroll
            for (int mf = 0; mf < 2; mf++) {
                int r = moff + 32 + mf * 16 + gid;
                a2[mf][0] = f2tf32(Asb[r * AST + k0 + tig]);
                a2[mf][1] = f2tf32(Asb[(r + 8) * AST + k0 + tig]);
                a2[mf][2] = f2tf32(Asb[r * AST + k0 + tig + 4]);
                a2[mf][3] = f2tf32(Asb[(r + 8) * AST + k0 + tig + 4]);
            }
            uint32_t b[4][2];
            #pragma unroll
            for (int nf = 0; nf < 4; nf++) {
                int nc = noff + nf * 8 + gid;
                b[nf][0] = f2tf32(Bsb[(k0 + tig) * BST + nc]);
                b[nf][1] = f2tf32(Bsb[(k0 + tig + 4) * BST + nc]);
            }
            #pragma unroll
            for (int nf = 0; nf < 4; nf++) {
                mma_tf32_16x8x8(acc[0][nf], a[0][0], a[0][1], a[0][2], a[0][3],
                                b[nf][0], b[nf][1]);
                mma_tf32_16x8x8(acc[1][nf], a[1][0], a[1][1], a[1][2], a[1][3],
                                b[nf][0], b[nf][1]);
                mma_tf32_16x8x8(acc[2][nf], a2[0][0], a2[0][1], a2[0][2], a2[0][3],
                                b[nf][0], b[nf][1]);
                mma_tf32_16x8x8(acc[3][nf], a2[1][0], a2[1][1], a2[1][2], a2[1][3],
                                b[nf][0], b[nf][1]);
            }
        }
        __syncthreads();
    }

    // epilogue
    #pragma unroll
    for (int mf = 0; mf < 4; mf++) {
        #pragma unroll
        for (int half = 0; half < 2; half++) {
            int row = m0 + moff + mf * 16 + gid + half * 8;
            float* crow = C + (size_t)row * N + n0 + noff;
            const float* brow_ = bias + n0 + noff;
            #pragma unroll
            for (int nf = 0; nf < 4; nf++) {
                int cl = nf * 8 + 2 * tig;
                float2 v;
                v.x = acc[mf][nf][half * 2 + 0] + brow_[cl];
                v.y = acc[mf][nf][half * 2 + 1] + brow_[cl + 1];
                if (act == 1) { v.x = gelu_tanh(v.x); v.y = gelu_tanh(v.y); }
                *reinterpret_cast<float2*>(crow + cl) = v;
            }
        }
    }
}

// ---------------------------------------------------------------------------
// Tensor-core flash attention. One block per (b,h); 8 warps each own 32 q rows.
// K^T, V staged as tf32 in smem; Q resident as pre-scaled a-frags.
// ---------------------------------------------------------------------------
#define KTS 264
#define VST 72
#define PST 36
#define ATN_U32 (64 * KTS + 256 * VST + 8 * 32 * PST + 256)
#define ATN_SMEM (ATN_U32 * 4)

__global__ __launch_bounds__(256) void attn_kernel(
    const float* __restrict__ qkv, const int* __restrict__ amask,
    float* __restrict__ out)
{
    extern __shared__ uint32_t ash[];
    uint32_t* Kt = ash;                    // [64][KTS]
    uint32_t* Vs = ash + 64 * KTS;         // [256][VST]
    uint32_t* Ps = Vs + 256 * VST;         // [8][32][PST]
    float* Ms = (float*)(Ps + 8 * 32 * PST);

    const int bh = blockIdx.x;
    const int b = bh / NHEAD;
    const int h = bh % NHEAD;
    const int tid = threadIdx.x;
    const int wid = tid >> 5;
    const int lane = tid & 31;
    const int gid = lane >> 2;
    const int tig = lane & 3;

    const float* base = qkv + (size_t)b * SEQ * (3 * HID);

    // stage K^T and V (tf32 bits), mask bias
    {
        int key = tid;
        const float* kr = base + (size_t)key * (3 * HID) + HID + h * HDIM;
        const float* vr = base + (size_t)key * (3 * HID) + 2 * HID + h * HDIM;
        #pragma unroll
        for (int d = 0; d < HDIM; d += 4) {
            float4 kv = *reinterpret_cast<const float4*>(kr + d);
            Kt[(d + 0) * KTS + key] = f2tf32(kv.x);
            Kt[(d + 1) * KTS + key] = f2tf32(kv.y);
            Kt[(d + 2) * KTS + key] = f2tf32(kv.z);
            Kt[(d + 3) * KTS + key] = f2tf32(kv.w);
            float4 vv = *reinterpret_cast<const float4*>(vr + d);
            uint4 u = make_uint4(f2tf32(vv.x), f2tf32(vv.y), f2tf32(vv.z), f2tf32(vv.w));
            *reinterpret_cast<uint4*>(&Vs[key * VST + d]) = u;
        }
        Ms[key] = (1.0f - (float)amask[b * SEQ + key]) * -1e9f;
    }

    // resident Q fragments, pre-scaled by 1/sqrt(HDIM)
    const int qbase = wid * 32;
    uint32_t aq[2][8][4];
    #pragma unroll
    for (int mf = 0; mf < 2; mf++) {
        const float* q0 = base + (size_t)(qbase + mf * 16 + gid) * (3 * HID) + h * HDIM;
        const float* q1 = q0 + (size_t)8 * (3 * HID);
        #pragma unroll
        for (int ks = 0; ks < 8; ks++) {
            aq[mf][ks][0] = f2tf32(q0[ks * 8 + tig] * 0.125f);
            aq[mf][ks][1] = f2tf32(q1[ks * 8 + tig] * 0.125f);
            aq[mf][ks][2] = f2tf32(q0[ks * 8 + tig + 4] * 0.125f);
            aq[mf][ks][3] = f2tf32(q1[ks * 8 + tig + 4] * 0.125f);
        }
    }
    __syncthreads();

    float mrun[4] = {-1e30f, -1e30f, -1e30f, -1e30f};
    float lrun[4] = {0.f, 0.f, 0.f, 0.f};
    float O[2][8][4];
    #pragma unroll
    for (int i = 0; i < 2; i++)
        #pragma unroll
        for (int j = 0; j < 8; j++)
            #pragma unroll
            for (int q = 0; q < 4; q++) O[i][j][q] = 0.f;

    uint32_t* Pw = Ps + wid * 32 * PST;

    #pragma unroll 1
    for (int kc = 0; kc < 8; kc++) {
        const int kb = kc * 32;

        // S = Q @ K^T chunk (32 keys)
        float sacc[2][4][4];
        #pragma unroll
        for (int i = 0; i < 2; i++)
            #pragma unroll
            for (int j = 0; j < 4; j++)
                #pragma unroll
                for (int q = 0; q < 4; q++) sacc[i][j][q] = 0.f;

        #pragma unroll
        for (int ks = 0; ks < 8; ks++) {
            int k0 = ks * 8;
            uint32_t bk[4][2];
            #pragma unroll
            for (int nf = 0; nf < 4; nf++) {
                bk[nf][0] = Kt[(k0 + tig) * KTS + kb + nf * 8 + gid];
                bk[nf][1] = Kt[(k0 + tig + 4) * KTS + kb + nf * 8 + gid];
            }
            #pragma unroll
            for (int mf = 0; mf < 2; mf++)
                #pragma unroll
                for (int nf = 0; nf < 4; nf++)
                    mma_tf32_16x8x8(sacc[mf][nf],
                        aq[mf][ks][0], aq[mf][ks][1], aq[mf][ks][2], aq[mf][ks][3],
                        bk[nf][0], bk[nf][1]);
        }

        // add mask bias
        #pragma unroll
        for (int nf = 0; nf < 4; nf++) {
            float mb0 = Ms[kb + nf * 8 + 2 * tig];
            float mb1 = Ms[kb + nf * 8 + 2 * tig + 1];
            #pragma unroll
            for (int mf = 0; mf < 2; mf++) {
                sacc[mf][nf][0] += mb0; sacc[mf][nf][1] += mb1;
                sacc[mf][nf][2] += mb0; sacc[mf][nf][3] += mb1;
            }
        }

        // online softmax per row slot
        #pragma unroll
        for (int rs = 0; rs < 4; rs++) {
            int mf = rs >> 1, cp = rs & 1;
            float lmax = -1e30f;
            #pragma unroll
            for (int nf = 0; nf < 4; nf++)
                lmax = fmaxf(lmax, fmaxf(sacc[mf][nf][2 * cp], sacc[mf][nf][2 * cp + 1]));
            lmax = fmaxf(lmax, __shfl_xor_sync(0xffffffffu, lmax, 1));
            lmax = fmaxf(lmax, __shfl_xor_sync(0xffffffffu, lmax, 2));
            float mnew = fmaxf(mrun[rs], lmax);
            float corr = __expf(mrun[rs] - mnew);
            float psum = 0.f;
            int prow = mf * 16 + gid + cp * 8;
            #pragma unroll
            for (int nf = 0; nf < 4; nf++) {
                uint32_t u0 = f2tf32(__expf(sacc[mf][nf][2 * cp] - mnew));
                uint32_t u1 = f2tf32(__expf(sacc[mf][nf][2 * cp + 1] - mnew));
                psum += __uint_as_float(u0) + __uint_as_float(u1);
                Pw[prow * PST + nf * 8 + 2 * tig] = u0;
                Pw[prow * PST + nf * 8 + 2 * tig + 1] = u1;
            }
            psum += __shfl_xor_sync(0xffffffffu, psum, 1);
            psum += __shfl_xor_sync(0xffffffffu, psum, 2);
            lrun[rs] = lrun[rs] * corr + psum;
            mrun[rs] = mnew;
            #pragma unroll
            for (int nf2 = 0; nf2 < 8; nf2++) {
                O[mf][nf2][2 * cp] *= corr;
                O[mf][nf2][2 * cp + 1] *= corr;
            }
        }
        __syncwarp();

        // O += P @ V
        #pragma unroll
        for (int ks2 = 0; ks2 < 4; ks2++) {
            int k0 = ks2 * 8;
            uint32_t ap[2][4];
            #pragma unroll
            for (int mf = 0; mf < 2; mf++) {
                int r = mf * 16 + gid;
                ap[mf][0] = Pw[r * PST + k0 + tig];
                ap[mf][1] = Pw[(r + 8) * PST + k0 + tig];
                ap[mf][2] = Pw[r * PST + k0 + tig + 4];
                ap[mf][3] = Pw[(r + 8) * PST + k0 + tig + 4];
            }
            #pragma unroll
            for (int nf2 = 0; nf2 < 8; nf2++) {
                uint32_t bv0 = Vs[(kb + k0 + tig) * VST + nf2 * 8 + gid];
                uint32_t bv1 = Vs[(kb + k0 + tig + 4) * VST + nf2 * 8 + gid];
                mma_tf32_16x8x8(O[0][nf2], ap[0][0], ap[0][1], ap[0][2], ap[0][3],
                                bv0, bv1);
                mma_tf32_16x8x8(O[1][nf2], ap[1][0], ap[1][1], ap[1][2], ap[1][3],
                                bv0, bv1);
            }
        }
        __syncwarp();
    }

    // write out
    float inv[4];
    #pragma unroll
    for (int rs = 0; rs < 4; rs++) inv[rs] = 1.0f / lrun[rs];
    #pragma unroll
    for (int mf = 0; mf < 2; mf++) {
        #pragma unroll
        for (int cp = 0; cp < 2; cp++) {
            int row = b * SEQ + qbase + mf * 16 + gid + cp * 8;
            float* orow = out + (size_t)row * HID + h * HDIM;
            float iv = inv[mf * 2 + cp];
            #pragma unroll
            for (int nf2 = 0; nf2 < 8; nf2++) {
                float2 v;
                v.x = O[mf][nf2][2 * cp] * iv;
                v.y = O[mf][nf2][2 * cp + 1] * iv;
                *reinterpret_cast<float2*>(orow + nf2 * 8 + 2 * tig) = v;
            }
        }
    }
}

// ---------------------------------------------------------------------------
// Warp-per-row LayerNorms (block = 8 warps = 8 rows)
// ---------------------------------------------------------------------------
__device__ __forceinline__ void warp_ln_write(
    float* dst, const float* v, const float* lns, const float* lnb,
    int lane, float mean, float inv)
{
    #pragma unroll
    for (int i = 0; i < 6; i++) {
        int c = i * 128 + lane * 4;
        float4 g = *reinterpret_cast<const float4*>(lns + c);
        float4 bq = *reinterpret_cast<const float4*>(lnb + c);
        float4 o;
        o.x = (v[i * 4 + 0] - mean) * inv * g.x + bq.x;
        o.y = (v[i * 4 + 1] - mean) * inv * g.y + bq.y;
        o.z = (v[i * 4 + 2] - mean) * inv * g.z + bq.z;
        o.w = (v[i * 4 + 3] - mean) * inv * g.w + bq.w;
        *reinterpret_cast<float4*>(dst + c) = o;
    }
}

__device__ __forceinline__ void warp_ln_stats(const float* v, float& mean, float& inv)
{
    float s = 0.f, sq = 0.f;
    #pragma unroll
    for (int j = 0; j < 24; j++) { s += v[j]; sq += v[j] * v[j]; }
    #pragma unroll
    for (int o = 16; o > 0; o >>= 1) {
        s  += __shfl_xor_sync(0xffffffffu, s, o);
        sq += __shfl_xor_sync(0xffffffffu, sq, o);
    }
    mean = s * (1.0f / HID);
    float var = sq * (1.0f / HID) - mean * mean;
    inv = rsqrtf(var + 1e-12f);
}

__global__ __launch_bounds__(256) void embed_ln_kernel(
    const int* __restrict__ ids, const float* __restrict__ wemb,
    const float* __restrict__ pemb, const float* __restrict__ lns,
    const float* __restrict__ lnb, float* __restrict__ xout)
{
    int wid = threadIdx.x >> 5, lane = threadIdx.x & 31;
    int row = blockIdx.x * 8 + wid;
    int spos = row & (SEQ - 1);
    int id = ids[row];
    const float* wr = wemb + (size_t)id * HID;
    const float* pr = pemb + (size_t)spos * HID;
    float v[24];
    #pragma unroll
    for (int i = 0; i < 6; i++) {
        int c = i * 128 + lane * 4;
        float4 a = *reinterpret_cast<const float4*>(wr + c);
        float4 p = *reinterpret_cast<const float4*>(pr + c);
        v[i * 4 + 0] = a.x + p.x; v[i * 4 + 1] = a.y + p.y;
        v[i * 4 + 2] = a.z + p.z; v[i * 4 + 3] = a.w + p.w;
    }
    float mean, inv;
    warp_ln_stats(v, mean, inv);
    warp_ln_write(xout + (size_t)row * HID, v, lns, lnb, lane, mean, inv);
}

__global__ __launch_bounds__(256) void resid_ln_kernel(
    float* __restrict__ x, const float* __restrict__ y,
    const float* __restrict__ lns, const float* __restrict__ lnb)
{
    int wid = threadIdx.x >> 5, lane = threadIdx.x & 31;
    int row = blockIdx.x * 8 + wid;
    float* xr = x + (size_t)row * HID;
    const float* yr = y + (size_t)row * HID;
    float v[24];
    #pragma unroll
    for (int i = 0; i < 6; i++) {
        int c = i * 128 + lane * 4;
        float4 a = *reinterpret_cast<const float4*>(xr + c);
        float4 bq = *reinterpret_cast<const float4*>(yr + c);
        v[i * 4 + 0] = a.x + bq.x; v[i * 4 + 1] = a.y + bq.y;
        v[i * 4 + 2] = a.z + bq.z; v[i * 4 + 3] = a.w + bq.w;
    }
    float mean, inv;
    warp_ln_stats(v, mean, inv);
    warp_ln_write(xr, v, lns, lnb, lane, mean, inv);
}

// ---------------------------------------------------------------------------
// Classifier: warp per row
// ---------------------------------------------------------------------------
__global__ __launch_bounds__(256) void cls_kernel(
    const float* __restrict__ x, const float* __restrict__ W,
    const float* __restrict__ bias, float* __restrict__ out)
{
    int wid = threadIdx.x >> 5, lane = threadIdx.x & 31;
    int row = blockIdx.x * 8 + wid;
    const float* xr = x + (size_t)row * HID;
    float acc[NTAGS];
    #pragma unroll
    for (int n = 0; n < NTAGS; n++) acc[n] = 0.f;
    #pragma unroll
    for (int i = 0; i < 24; i++) {
        int k = i * 32 + lane;
        float xv = xr[k];
        const float* wr = W + k * NTAGS;
        #pragma unroll
        for (int n = 0; n < NTAGS; n++) acc[n] += xv * wr[n];
    }
    #pragma unroll
    for (int n = 0; n < NTAGS; n++) {
        #pragma unroll
        for (int o = 16; o > 0; o >>= 1)
            acc[n] += __shfl_xor_sync(0xffffffffu, acc[n], o);
    }
    if (lane < NTAGS)
        out[(size_t)row * NTAGS + lane] = acc[lane] + bias[lane];
}

// ---------------------------------------------------------------------------
// CRF: one warp per batch element
// ---------------------------------------------------------------------------
__global__ __launch_bounds__(32) void crf_kernel(
    const float* __restrict__ logits, const int* __restrict__ labels,
    const float* __restrict__ cstart, const float* __restrict__ cend,
    const float* __restrict__ ctrans, float* __restrict__ nmd)
{
    int b = blockIdx.x;
    int lane = threadIdx.x;
    const float* lg = logits + (size_t)b * SEQ * NTAGS;
    const int* lab = labels + b * SEQ;

    float part = 0.f;
    int cnt = 0;
    for (int s = lane; s < SEQ; s += 32) {
        int lv = lab[s];
        bool mk = (s == 0) || (lv != -100);
        cnt += mk ? 1 : 0;
        if (s >= 1 && mk) {
            int lp = lab[s - 1]; int tp = (lp == -100) ? 0 : lp;
            int tc = (lv == -100) ? 0 : lv;
            part += ctrans[tp * NTAGS + tc] + lg[s * NTAGS + tc];
        }
    }
    #pragma unroll
    for (int o = 16; o > 0; o >>= 1) {
        part += __shfl_xor_sync(0xffffffffu, part, o);
        cnt  += __shfl_xor_sync(0xffffffffu, cnt, o);
    }

    int t = (lane < NTAGS) ? lane : 0;
    float tt[NTAGS];
    #pragma unroll
    for (int i = 0; i < NTAGS; i++) tt[i] = ctrans[i * NTAGS + t];
    float score = cstart[t] + lg[t];

    for (int s = 1; s < SEQ; s++) {
        float e = lg[s * NTAGS + t];
        float v[NTAGS];
        float vmax = -1e30f;
        #pragma unroll
        for (int i = 0; i < NTAGS; i++) {
            float si = __shfl_sync(0xffffffffu, score, i);
            v[i] = si + tt[i];
            vmax = fmaxf(vmax, v[i]);
        }
        float smv = 0.f;
        #pragma unroll
        for (int i = 0; i < NTAGS; i++) smv += __expf(v[i] - vmax);
        float nxt = vmax + __logf(smv) + e;
        bool mk = (lab[s] != -100);
        score = mk ? nxt : score;
    }

    float fin = score + cend[t];
    float gmax = -1e30f;
    #pragma unroll
    for (int i = 0; i < NTAGS; i++)
        gmax = fmaxf(gmax, __shfl_sync(0xffffffffu, fin, i));
    float gs = 0.f;
    #pragma unroll
    for (int i = 0; i < NTAGS; i++)
        gs += __expf(__shfl_sync(0xffffffffu, fin, i) - gmax);
    float denom = gmax + __logf(gs);

    if (lane == 0) {
        int l0 = lab[0]; int t0 = (l0 == -100) ? 0 : l0;
        int seq_end = cnt - 1;
        int le = lab[seq_end]; int te = (le == -100) ? 0 : le;
        float num = part + cstart[t0] + lg[t0] + cend[te];
        nmd[b] = num - denom;
    }
}

__global__ __launch_bounds__(32) void loss_kernel(
    const float* __restrict__ nmd, float* __restrict__ out)
{
    int lane = threadIdx.x;
    float v = (lane < BATCH) ? nmd[lane] : 0.f;
    #pragma unroll
    for (int o = 16; o > 0; o >>= 1) v += __shfl_xor_sync(0xffffffffu, v, o);
    if (lane == 0) out[0] = -(v * (1.0f / BATCH));
}

// ---------------------------------------------------------------------------
// Launcher
// ---------------------------------------------------------------------------
extern "C" void kernel_launch(void* const* d_in, const int* in_sizes, int n_in,
                              void* d_out, int out_size)
{
    const int*   input_ids = (const int*)d_in[0];
    const int*   amask     = (const int*)d_in[1];
    const int*   labels    = (const int*)d_in[2];
    const float* word_emb  = (const float*)d_in[3];
    const float* pos_emb   = (const float*)d_in[4];
    const float* eln_s     = (const float*)d_in[5];
    const float* eln_b     = (const float*)d_in[6];
    const float* Wqkv      = (const float*)d_in[7];
    const float* bqkv      = (const float*)d_in[8];
    const float* Wo        = (const float*)d_in[9];
    const float* bo        = (const float*)d_in[10];
    const float* ln1s      = (const float*)d_in[11];
    const float* ln1b      = (const float*)d_in[12];
    const float* Wff1      = (const float*)d_in[13];
    const float* bff1      = (const float*)d_in[14];
    const float* Wff2      = (const float*)d_in[15];
    const float* bff2      = (const float*)d_in[16];
    const float* ln2s      = (const float*)d_in[17];
    const float* ln2b      = (const float*)d_in[18];
    const float* Wcls      = (const float*)d_in[19];
    const float* bcls      = (const float*)d_in[20];
    const float* cstart    = (const float*)d_in[21];
    const float* cend      = (const float*)d_in[22];
    const float* ctrans    = (const float*)d_in[23];
    float* out = (float*)d_out;

    float *x, *qkv, *attn, *ffn, *tmp, *nmd;
    cudaGetSymbolAddress((void**)&x,    g_x);
    cudaGetSymbolAddress((void**)&qkv,  g_qkv);
    cudaGetSymbolAddress((void**)&attn, g_attn);
    cudaGetSymbolAddress((void**)&ffn,  g_ffn);
    cudaGetSymbolAddress((void**)&tmp,  g_tmp);
    cudaGetSymbolAddress((void**)&nmd,  g_nmd);

    cudaFuncSetAttribute(gemm_tc_kernel,
        cudaFuncAttributeMaxDynamicSharedMemorySize, GEMM_DSMEM);
    cudaFuncSetAttribute(attn_kernel,
        cudaFuncAttributeMaxDynamicSharedMemorySize, ATN_SMEM);

    embed_ln_kernel<<<NTOK / 8, 256>>>(input_ids, word_emb, pos_emb, eln_s, eln_b, x);

    for (int L = 0; L < NLAYER; L++) {
        gemm_tc_kernel<<<dim3(3 * HID / 128, NTOK / 128), 256, GEMM_DSMEM>>>(
            x, Wqkv + (size_t)L * HID * 3 * HID, bqkv + (size_t)L * 3 * HID,
            qkv, NTOK, 3 * HID, HID, 0);

        attn_kernel<<<BATCH * NHEAD, 256, ATN_SMEM>>>(qkv, amask, attn);

        gemm_tc_kernel<<<dim3(HID / 128, NTOK / 128), 256, GEMM_DSMEM>>>(
            attn, Wo + (size_t)L * HID * HID, bo + (size_t)L * HID,
            tmp, NTOK, HID, HID, 0);

        resid_ln_kernel<<<NTOK / 8, 256>>>(x, tmp,
            ln1s + (size_t)L * HID, ln1b + (size_t)L * HID);

        gemm_tc_kernel<<<dim3(FFN / 128, NTOK / 128), 256, GEMM_DSMEM>>>(
            x, Wff1 + (size_t)L * HID * FFN, bff1 + (size_t)L * FFN,
            ffn, NTOK, FFN, HID, 1);

        gemm_tc_kernel<<<dim3(HID / 128, NTOK / 128), 256, GEMM_DSMEM>>>(
            ffn, Wff2 + (size_t)L * FFN * HID, bff2 + (size_t)L * HID,
            tmp, NTOK, HID, FFN, 0);

        resid_ln_kernel<<<NTOK / 8, 256>>>(x, tmp,
            ln2s + (size_t)L * HID, ln2b + (size_t)L * HID);
    }

    cls_kernel<<<NTOK / 8, 256>>>(x, Wcls, bcls, out + 1);
    crf_kernel<<<BATCH, 32>>>(out + 1, labels, cstart, cend, ctrans, nmd);
    loss_kernel<<<1, 32>>>(nmd, out);
}

// round 6
// speedup vs baseline: 3.8848x; 1.0272x over previous
#include <cuda_runtime.h>
#include <cuda_bf16.h>
#include <math.h>
#include <stdint.h>

// ---------------------------------------------------------------------------
// Problem constants
// ---------------------------------------------------------------------------
#define BATCH 16
#define SEQ 256
#define NTOK (BATCH * SEQ)          // 4096
#define HID 768
#define NHEAD 12
#define HDIM 64
#define FFN 3072
#define NLAYER 6
#define NTAGS 9

// Weight scratch offsets (floats)
#define W_QKV_OFF 0
#define W_QKV_SZ  (NLAYER * HID * 3 * HID)          // 10,616,832
#define W_WO_OFF  (W_QKV_OFF + W_QKV_SZ)
#define W_WO_SZ   (NLAYER * HID * HID)              // 3,538,944
#define W_FF1_OFF (W_WO_OFF + W_WO_SZ)
#define W_FF1_SZ  (NLAYER * HID * FFN)              // 14,155,776
#define W_FF2_OFF (W_FF1_OFF + W_FF1_SZ)
#define W_FF2_SZ  (NLAYER * FFN * HID)              // 14,155,776
#define W_TOTAL   (W_FF2_OFF + W_FF2_SZ)

// ---------------------------------------------------------------------------
// Scratch (device globals; no allocation allowed)
// ---------------------------------------------------------------------------
__device__ float g_x[NTOK * HID];
__device__ float g_qkv[NTOK * 3 * HID];
__device__ float g_attn[NTOK * HID];
__device__ float g_ffn[NTOK * FFN];
__device__ float g_tmp[NTOK * HID];
__device__ float g_nmd[BATCH];
__device__ float g_w[W_TOTAL];     // tf32-rounded weights

// ---------------------------------------------------------------------------
// helpers
// ---------------------------------------------------------------------------
__device__ __forceinline__ uint32_t smem_u32(const void* p) {
    uint32_t a;
    asm("{ .reg .u64 t; cvta.to.shared.u64 t, %1; cvt.u32.u64 %0, t; }"
        : "=r"(a) : "l"(p));
    return a;
}

__device__ __forceinline__ uint32_t f2tf32(float x) {
    uint32_t r;
    asm("cvt.rna.tf32.f32 %0, %1;" : "=r"(r) : "f"(x));
    return r;
}
__device__ __forceinline__ float tf32r(float x) {   // round fp32 -> tf32-representable fp32
    return __uint_as_float(f2tf32(x));
}

__device__ __forceinline__ void mma_tf32_16x8x8(
    float* c, uint32_t a0, uint32_t a1, uint32_t a2, uint32_t a3,
    uint32_t b0, uint32_t b1)
{
    asm volatile(
        "mma.sync.aligned.m16n8k8.row.col.f32.tf32.tf32.f32 "
        "{%0,%1,%2,%3}, {%4,%5,%6,%7}, {%8,%9}, {%0,%1,%2,%3};"
        : "+f"(c[0]), "+f"(c[1]), "+f"(c[2]), "+f"(c[3])
        : "r"(a0), "r"(a1), "r"(a2), "r"(a3), "r"(b0), "r"(b1));
}

__device__ __forceinline__ float gelu_tanh(float v) {
    float c = 0.7978845608028654f;
    float u = c * (v + 0.044715f * v * v * v);
    return 0.5f * v * (1.0f + tanhf(u));
}

#define CP_ASYNC16(dst, src) \
    asm volatile("cp.async.cg.shared.global [%0], [%1], 16;" \
        :: "r"(dst), "l"(src) : "memory")
#define CP_COMMIT() asm volatile("cp.async.commit_group;" ::: "memory")
#define CP_WAIT2()  asm volatile("cp.async.wait_group 2;" ::: "memory")

// ---------------------------------------------------------------------------
// One-shot weight tf32 rounding (grid-stride, float4)
// ---------------------------------------------------------------------------
__global__ __launch_bounds__(256) void conv_tf32_kernel(
    const float* __restrict__ src, float* __restrict__ dst, int n4)
{
    int i = blockIdx.x * blockDim.x + threadIdx.x;
    int stride = gridDim.x * blockDim.x;
    for (; i < n4; i += stride) {
        float4 v = reinterpret_cast<const float4*>(src)[i];
        v.x = tf32r(v.x); v.y = tf32r(v.y); v.z = tf32r(v.z); v.w = tf32r(v.w);
        reinterpret_cast<float4*>(dst)[i] = v;
    }
}

// ---------------------------------------------------------------------------
// tf32 tensor-core GEMM with cp.async 3-stage pipeline.
// Operands must be tf32-representable fp32 (raw-bit feed, zero cvt in loop).
// C[M,N] = A[M,K] @ B[K,N] + bias   (act=1 -> gelu). Output tf32-rounded.
// ---------------------------------------------------------------------------
#define AST 36
#define BST 136
#define A_STAGE (128 * AST)
#define B_STAGE (32 * BST)
#define GEMM_DSMEM ((3 * A_STAGE + 3 * B_STAGE) * 4)

__global__ __launch_bounds__(256) void gemm_tc_kernel(
    const float* __restrict__ A, const float* __restrict__ B,
    const float* __restrict__ bias, float* __restrict__ C,
    int M, int N, int K, int act)
{
    extern __shared__ float gsm[];
    float* AsB = gsm;                 // [3][128][AST]
    float* BsB = gsm + 3 * A_STAGE;   // [3][32][BST]
    const uint32_t s_as = smem_u32(AsB);
    const uint32_t s_bs = smem_u32(BsB);

    const int tid = threadIdx.x;
    const int wid = tid >> 5;
    const int lane = tid & 31;
    const int gid = lane >> 2;
    const int tig = lane & 3;
    const int moff = (wid >> 2) * 64;
    const int noff = (wid & 3) * 32;

    const int m0 = blockIdx.y * 128;
    const int n0 = blockIdx.x * 128;

    const int ar = tid >> 3, ac = (tid & 7) * 4;
    const int br = tid >> 5, bc = (tid & 31) * 4;

    float acc[4][4][4];
    #pragma unroll
    for (int i = 0; i < 4; i++)
        #pragma unroll
        for (int j = 0; j < 4; j++)
            #pragma unroll
            for (int q = 0; q < 4; q++) acc[i][j][q] = 0.f;

    const int nch = K >> 5;

    auto issue = [&](int stage, int kc) {
        #pragma unroll
        for (int i = 0; i < 4; i++) {
            int r = i * 32 + ar;
            uint32_t d = s_as + (uint32_t)(stage * A_STAGE + r * AST + ac) * 4u;
            const float* s = A + (size_t)(m0 + r) * K + kc + ac;
            CP_ASYNC16(d, s);
        }
        #pragma unroll
        for (int i = 0; i < 4; i++) {
            int r = i * 8 + br;
            uint32_t d = s_bs + (uint32_t)(stage * B_STAGE + r * BST + bc) * 4u;
            const float* s = B + (size_t)(kc + r) * N + n0 + bc;
            CP_ASYNC16(d, s);
        }
        CP_COMMIT();
    };

    issue(0, 0);
    issue(1, 32);

    #pragma unroll 1
    for (int c = 0; c < nch; c++) {
        if (c + 2 < nch) issue((c + 2) % 3, (c + 2) * 32);
        else CP_COMMIT();
        CP_WAIT2();
        __syncthreads();

        const uint32_t* Asb = reinterpret_cast<const uint32_t*>(AsB + (c % 3) * A_STAGE);
        const uint32_t* Bsb = reinterpret_cast<const uint32_t*>(BsB + (c % 3) * B_STAGE);

        #pragma unroll
        for (int ks = 0; ks < 4; ks++) {
            int k0 = ks * 8;
            uint32_t a[2][4];
            #pragma unroll
            for (int mf = 0; mf < 2; mf++) {
                int r = moff + mf * 16 + gid;
                a[mf][0] = Asb[r * AST + k0 + tig];
                a[mf][1] = Asb[(r + 8) * AST + k0 + tig];
                a[mf][2] = Asb[r * AST + k0 + tig + 4];
                a[mf][3] = Asb[(r + 8) * AST + k0 + tig + 4];
            }
            uint32_t a2[2][4];
            #pragma unroll
            for (int mf = 0; mf < 2; mf++) {
                int r = moff + 32 + mf * 16 + gid;
                a2[mf][0] = Asb[r * AST + k0 + tig];
                a2[mf][1] = Asb[(r + 8) * AST + k0 + tig];
                a2[mf][2] = Asb[r * AST + k0 + tig + 4];
                a2[mf][3] = Asb[(r + 8) * AST + k0 + tig + 4];
            }
            uint32_t b[4][2];
            #pragma unroll
            for (int nf = 0; nf < 4; nf++) {
                int nc = noff + nf * 8 + gid;
                b[nf][0] = Bsb[(k0 + tig) * BST + nc];
                b[nf][1] = Bsb[(k0 + tig + 4) * BST + nc];
            }
            #pragma unroll
            for (int nf = 0; nf < 4; nf++) {
                mma_tf32_16x8x8(acc[0][nf], a[0][0], a[0][1], a[0][2], a[0][3],
                                b[nf][0], b[nf][1]);
                mma_tf32_16x8x8(acc[1][nf], a[1][0], a[1][1], a[1][2], a[1][3],
                                b[nf][0], b[nf][1]);
                mma_tf32_16x8x8(acc[2][nf], a2[0][0], a2[0][1], a2[0][2], a2[0][3],
                                b[nf][0], b[nf][1]);
                mma_tf32_16x8x8(acc[3][nf], a2[1][0], a2[1][1], a2[1][2], a2[1][3],
                                b[nf][0], b[nf][1]);
            }
        }
        __syncthreads();
    }

    // epilogue (outputs tf32-rounded so consumers can raw-bit feed)
    #pragma unroll
    for (int mf = 0; mf < 4; mf++) {
        #pragma unroll
        for (int half = 0; half < 2; half++) {
            int row = m0 + moff + mf * 16 + gid + half * 8;
            float* crow = C + (size_t)row * N + n0 + noff;
            const float* brow_ = bias + n0 + noff;
            #pragma unroll
            for (int nf = 0; nf < 4; nf++) {
                int cl = nf * 8 + 2 * tig;
                float vx = acc[mf][nf][half * 2 + 0] + brow_[cl];
                float vy = acc[mf][nf][half * 2 + 1] + brow_[cl + 1];
                if (act == 1) { vx = gelu_tanh(vx); vy = gelu_tanh(vy); }
                float2 v;
                v.x = tf32r(vx);
                v.y = tf32r(vy);
                *reinterpret_cast<float2*>(crow + cl) = v;
            }
        }
    }
}

// ---------------------------------------------------------------------------
// Tensor-core flash attention. One block per (b,h); 8 warps each own 32 q rows.
// qkv is tf32-rounded by the QKV GEMM epilogue -> raw-bit staging (no cvt).
// ---------------------------------------------------------------------------
#define KTS 264
#define VST 72
#define PST 36
#define ATN_U32 (64 * KTS + 256 * VST + 8 * 32 * PST + 256)
#define ATN_SMEM (ATN_U32 * 4)

__global__ __launch_bounds__(256) void attn_kernel(
    const float* __restrict__ qkv, const int* __restrict__ amask,
    float* __restrict__ out)
{
    extern __shared__ uint32_t ash[];
    uint32_t* Kt = ash;                    // [64][KTS]
    uint32_t* Vs = ash + 64 * KTS;         // [256][VST]
    uint32_t* Ps = Vs + 256 * VST;         // [8][32][PST]
    float* Ms = (float*)(Ps + 8 * 32 * PST);

    const int bh = blockIdx.x;
    const int b = bh / NHEAD;
    const int h = bh % NHEAD;
    const int tid = threadIdx.x;
    const int wid = tid >> 5;
    const int lane = tid & 31;
    const int gid = lane >> 2;
    const int tig = lane & 3;

    const float* base = qkv + (size_t)b * SEQ * (3 * HID);

    // stage K^T and V (raw tf32 bits), mask bias
    {
        int key = tid;
        const uint32_t* kr = reinterpret_cast<const uint32_t*>(
            base + (size_t)key * (3 * HID) + HID + h * HDIM);
        const uint32_t* vr = reinterpret_cast<const uint32_t*>(
            base + (size_t)key * (3 * HID) + 2 * HID + h * HDIM);
        #pragma unroll
        for (int d = 0; d < HDIM; d += 4) {
            uint4 kv = *reinterpret_cast<const uint4*>(kr + d);
            Kt[(d + 0) * KTS + key] = kv.x;
            Kt[(d + 1) * KTS + key] = kv.y;
            Kt[(d + 2) * KTS + key] = kv.z;
            Kt[(d + 3) * KTS + key] = kv.w;
            *reinterpret_cast<uint4*>(&Vs[key * VST + d]) =
                *reinterpret_cast<const uint4*>(vr + d);
        }
        Ms[key] = (1.0f - (float)amask[b * SEQ + key]) * -1e9f;
    }

    // resident Q fragments, pre-scaled by 0.125 (exact power of two)
    const int qbase = wid * 32;
    uint32_t aq[2][8][4];
    #pragma unroll
    for (int mf = 0; mf < 2; mf++) {
        const float* q0 = base + (size_t)(qbase + mf * 16 + gid) * (3 * HID) + h * HDIM;
        const float* q1 = q0 + (size_t)8 * (3 * HID);
        #pragma unroll
        for (int ks = 0; ks < 8; ks++) {
            aq[mf][ks][0] = __float_as_uint(q0[ks * 8 + tig] * 0.125f);
            aq[mf][ks][1] = __float_as_uint(q1[ks * 8 + tig] * 0.125f);
            aq[mf][ks][2] = __float_as_uint(q0[ks * 8 + tig + 4] * 0.125f);
            aq[mf][ks][3] = __float_as_uint(q1[ks * 8 + tig + 4] * 0.125f);
        }
    }
    __syncthreads();

    float mrun[4] = {-1e30f, -1e30f, -1e30f, -1e30f};
    float lrun[4] = {0.f, 0.f, 0.f, 0.f};
    float O[2][8][4];
    #pragma unroll
    for (int i = 0; i < 2; i++)
        #pragma unroll
        for (int j = 0; j < 8; j++)
            #pragma unroll
            for (int q = 0; q < 4; q++) O[i][j][q] = 0.f;

    uint32_t* Pw = Ps + wid * 32 * PST;

    #pragma unroll 1
    for (int kc = 0; kc < 8; kc++) {
        const int kb = kc * 32;

        float sacc[2][4][4];
        #pragma unroll
        for (int i = 0; i < 2; i++)
            #pragma unroll
            for (int j = 0; j < 4; j++)
                #pragma unroll
                for (int q = 0; q < 4; q++) sacc[i][j][q] = 0.f;

        #pragma unroll
        for (int ks = 0; ks < 8; ks++) {
            int k0 = ks * 8;
            uint32_t bk[4][2];
            #pragma unroll
            for (int nf = 0; nf < 4; nf++) {
                bk[nf][0] = Kt[(k0 + tig) * KTS + kb + nf * 8 + gid];
                bk[nf][1] = Kt[(k0 + tig + 4) * KTS + kb + nf * 8 + gid];
            }
            #pragma unroll
            for (int mf = 0; mf < 2; mf++)
                #pragma unroll
                for (int nf = 0; nf < 4; nf++)
                    mma_tf32_16x8x8(sacc[mf][nf],
                        aq[mf][ks][0], aq[mf][ks][1], aq[mf][ks][2], aq[mf][ks][3],
                        bk[nf][0], bk[nf][1]);
        }

        #pragma unroll
        for (int nf = 0; nf < 4; nf++) {
            float mb0 = Ms[kb + nf * 8 + 2 * tig];
            float mb1 = Ms[kb + nf * 8 + 2 * tig + 1];
            #pragma unroll
            for (int mf = 0; mf < 2; mf++) {
                sacc[mf][nf][0] += mb0; sacc[mf][nf][1] += mb1;
                sacc[mf][nf][2] += mb0; sacc[mf][nf][3] += mb1;
            }
        }

        #pragma unroll
        for (int rs = 0; rs < 4; rs++) {
            int mf = rs >> 1, cp = rs & 1;
            float lmax = -1e30f;
            #pragma unroll
            for (int nf = 0; nf < 4; nf++)
                lmax = fmaxf(lmax, fmaxf(sacc[mf][nf][2 * cp], sacc[mf][nf][2 * cp + 1]));
            lmax = fmaxf(lmax, __shfl_xor_sync(0xffffffffu, lmax, 1));
            lmax = fmaxf(lmax, __shfl_xor_sync(0xffffffffu, lmax, 2));
            float mnew = fmaxf(mrun[rs], lmax);
            float corr = __expf(mrun[rs] - mnew);
            float psum = 0.f;
            int prow = mf * 16 + gid + cp * 8;
            #pragma unroll
            for (int nf = 0; nf < 4; nf++) {
                uint32_t u0 = f2tf32(__expf(sacc[mf][nf][2 * cp] - mnew));
                uint32_t u1 = f2tf32(__expf(sacc[mf][nf][2 * cp + 1] - mnew));
                psum += __uint_as_float(u0) + __uint_as_float(u1);
                Pw[prow * PST + nf * 8 + 2 * tig] = u0;
                Pw[prow * PST + nf * 8 + 2 * tig + 1] = u1;
            }
            psum += __shfl_xor_sync(0xffffffffu, psum, 1);
            psum += __shfl_xor_sync(0xffffffffu, psum, 2);
            lrun[rs] = lrun[rs] * corr + psum;
            mrun[rs] = mnew;
            #pragma unroll
            for (int nf2 = 0; nf2 < 8; nf2++) {
                O[mf][nf2][2 * cp] *= corr;
                O[mf][nf2][2 * cp + 1] *= corr;
            }
        }
        __syncwarp();

        #pragma unroll
        for (int ks2 = 0; ks2 < 4; ks2++) {
            int k0 = ks2 * 8;
            uint32_t ap[2][4];
            #pragma unroll
            for (int mf = 0; mf < 2; mf++) {
                int r = mf * 16 + gid;
                ap[mf][0] = Pw[r * PST + k0 + tig];
                ap[mf][1] = Pw[(r + 8) * PST + k0 + tig];
                ap[mf][2] = Pw[r * PST + k0 + tig + 4];
                ap[mf][3] = Pw[(r + 8) * PST + k0 + tig + 4];
            }
            #pragma unroll
            for (int nf2 = 0; nf2 < 8; nf2++) {
                uint32_t bv0 = Vs[(kb + k0 + tig) * VST + nf2 * 8 + gid];
                uint32_t bv1 = Vs[(kb + k0 + tig + 4) * VST + nf2 * 8 + gid];
                mma_tf32_16x8x8(O[0][nf2], ap[0][0], ap[0][1], ap[0][2], ap[0][3],
                                bv0, bv1);
                mma_tf32_16x8x8(O[1][nf2], ap[1][0], ap[1][1], ap[1][2], ap[1][3],
                                bv0, bv1);
            }
        }
        __syncwarp();
    }

    float inv[4];
    #pragma unroll
    for (int rs = 0; rs < 4; rs++) inv[rs] = 1.0f / lrun[rs];
    #pragma unroll
    for (int mf = 0; mf < 2; mf++) {
        #pragma unroll
        for (int cp = 0; cp < 2; cp++) {
            int row = b * SEQ + qbase + mf * 16 + gid + cp * 8;
            float* orow = out + (size_t)row * HID + h * HDIM;
            float iv = inv[mf * 2 + cp];
            #pragma unroll
            for (int nf2 = 0; nf2 < 8; nf2++) {
                float2 v;
                v.x = tf32r(O[mf][nf2][2 * cp] * iv);
                v.y = tf32r(O[mf][nf2][2 * cp + 1] * iv);
                *reinterpret_cast<float2*>(orow + nf2 * 8 + 2 * tig) = v;
            }
        }
    }
}

// ---------------------------------------------------------------------------
// Warp-per-row LayerNorms (block = 8 warps = 8 rows); outputs tf32-rounded
// ---------------------------------------------------------------------------
__device__ __forceinline__ void warp_ln_write(
    float* dst, const float* v, const float* lns, const float* lnb,
    int lane, float mean, float inv)
{
    #pragma unroll
    for (int i = 0; i < 6; i++) {
        int c = i * 128 + lane * 4;
        float4 g = *reinterpret_cast<const float4*>(lns + c);
        float4 bq = *reinterpret_cast<const float4*>(lnb + c);
        float4 o;
        o.x = tf32r((v[i * 4 + 0] - mean) * inv * g.x + bq.x);
        o.y = tf32r((v[i * 4 + 1] - mean) * inv * g.y + bq.y);
        o.z = tf32r((v[i * 4 + 2] - mean) * inv * g.z + bq.z);
        o.w = tf32r((v[i * 4 + 3] - mean) * inv * g.w + bq.w);
        *reinterpret_cast<float4*>(dst + c) = o;
    }
}

__device__ __forceinline__ void warp_ln_stats(const float* v, float& mean, float& inv)
{
    float s = 0.f, sq = 0.f;
    #pragma unroll
    for (int j = 0; j < 24; j++) { s += v[j]; sq += v[j] * v[j]; }
    #pragma unroll
    for (int o = 16; o > 0; o >>= 1) {
        s  += __shfl_xor_sync(0xffffffffu, s, o);
        sq += __shfl_xor_sync(0xffffffffu, sq, o);
    }
    mean = s * (1.0f / HID);
    float var = sq * (1.0f / HID) - mean * mean;
    inv = rsqrtf(var + 1e-12f);
}

__global__ __launch_bounds__(256) void embed_ln_kernel(
    const int* __restrict__ ids, const float* __restrict__ wemb,
    const float* __restrict__ pemb, const float* __restrict__ lns,
    const float* __restrict__ lnb, float* __restrict__ xout)
{
    int wid = threadIdx.x >> 5, lane = threadIdx.x & 31;
    int row = blockIdx.x * 8 + wid;
    int spos = row & (SEQ - 1);
    int id = ids[row];
    const float* wr = wemb + (size_t)id * HID;
    const float* pr = pemb + (size_t)spos * HID;
    float v[24];
    #pragma unroll
    for (int i = 0; i < 6; i++) {
        int c = i * 128 + lane * 4;
        float4 a = *reinterpret_cast<const float4*>(wr + c);
        float4 p = *reinterpret_cast<const float4*>(pr + c);
        v[i * 4 + 0] = a.x + p.x; v[i * 4 + 1] = a.y + p.y;
        v[i * 4 + 2] = a.z + p.z; v[i * 4 + 3] = a.w + p.w;
    }
    float mean, inv;
    warp_ln_stats(v, mean, inv);
    warp_ln_write(xout + (size_t)row * HID, v, lns, lnb, lane, mean, inv);
}

__global__ __launch_bounds__(256) void resid_ln_kernel(
    float* __restrict__ x, const float* __restrict__ y,
    const float* __restrict__ lns, const float* __restrict__ lnb)
{
    int wid = threadIdx.x >> 5, lane = threadIdx.x & 31;
    int row = blockIdx.x * 8 + wid;
    float* xr = x + (size_t)row * HID;
    const float* yr = y + (size_t)row * HID;
    float v[24];
    #pragma unroll
    for (int i = 0; i < 6; i++) {
        int c = i * 128 + lane * 4;
        float4 a = *reinterpret_cast<const float4*>(xr + c);
        float4 bq = *reinterpret_cast<const float4*>(yr + c);
        v[i * 4 + 0] = a.x + bq.x; v[i * 4 + 1] = a.y + bq.y;
        v[i * 4 + 2] = a.z + bq.z; v[i * 4 + 3] = a.w + bq.w;
    }
    float mean, inv;
    warp_ln_stats(v, mean, inv);
    warp_ln_write(xr, v, lns, lnb, lane, mean, inv);
}

// ---------------------------------------------------------------------------
// Classifier: warp per row (fp32 exact)
// ---------------------------------------------------------------------------
__global__ __launch_bounds__(256) void cls_kernel(
    const float* __restrict__ x, const float* __restrict__ W,
    const float* __restrict__ bias, float* __restrict__ out)
{
    int wid = threadIdx.x >> 5, lane = threadIdx.x & 31;
    int row = blockIdx.x * 8 + wid;
    const float* xr = x + (size_t)row * HID;
    float acc[NTAGS];
    #pragma unroll
    for (int n = 0; n < NTAGS; n++) acc[n] = 0.f;
    #pragma unroll
    for (int i = 0; i < 24; i++) {
        int k = i * 32 + lane;
        float xv = xr[k];
        const float* wr = W + k * NTAGS;
        #pragma unroll
        for (int n = 0; n < NTAGS; n++) acc[n] += xv * wr[n];
    }
    #pragma unroll
    for (int n = 0; n < NTAGS; n++) {
        #pragma unroll
        for (int o = 16; o > 0; o >>= 1)
            acc[n] += __shfl_xor_sync(0xffffffffu, acc[n], o);
    }
    if (lane < NTAGS)
        out[(size_t)row * NTAGS + lane] = acc[lane] + bias[lane];
}

// ---------------------------------------------------------------------------
// CRF: one warp per batch element
// ---------------------------------------------------------------------------
__global__ __launch_bounds__(32) void crf_kernel(
    const float* __restrict__ logits, const int* __restrict__ labels,
    const float* __restrict__ cstart, const float* __restrict__ cend,
    const float* __restrict__ ctrans, float* __restrict__ nmd)
{
    int b = blockIdx.x;
    int lane = threadIdx.x;
    const float* lg = logits + (size_t)b * SEQ * NTAGS;
    const int* lab = labels + b * SEQ;

    float part = 0.f;
    int cnt = 0;
    for (int s = lane; s < SEQ; s += 32) {
        int lv = lab[s];
        bool mk = (s == 0) || (lv != -100);
        cnt += mk ? 1 : 0;
        if (s >= 1 && mk) {
            int lp = lab[s - 1]; int tp = (lp == -100) ? 0 : lp;
            int tc = (lv == -100) ? 0 : lv;
            part += ctrans[tp * NTAGS + tc] + lg[s * NTAGS + tc];
        }
    }
    #pragma unroll
    for (int o = 16; o > 0; o >>= 1) {
        part += __shfl_xor_sync(0xffffffffu, part, o);
        cnt  += __shfl_xor_sync(0xffffffffu, cnt, o);
    }

    int t = (lane < NTAGS) ? lane : 0;
    float tt[NTAGS];
    #pragma unroll
    for (int i = 0; i < NTAGS; i++) tt[i] = ctrans[i * NTAGS + t];
    float score = cstart[t] + lg[t];

    for (int s = 1; s < SEQ; s++) {
        float e = lg[s * NTAGS + t];
        float v[NTAGS];
        float vmax = -1e30f;
        #pragma unroll
        for (int i = 0; i < NTAGS; i++) {
            float si = __shfl_sync(0xffffffffu, score, i);
            v[i] = si + tt[i];
            vmax = fmaxf(vmax, v[i]);
        }
        float smv = 0.f;
        #pragma unroll
        for (int i = 0; i < NTAGS; i++) smv += __expf(v[i] - vmax);
        float nxt = vmax + __logf(smv) + e;
        bool mk = (lab[s] != -100);
        score = mk ? nxt : score;
    }

    float fin = score + cend[t];
    float gmax = -1e30f;
    #pragma unroll
    for (int i = 0; i < NTAGS; i++)
        gmax = fmaxf(gmax, __shfl_sync(0xffffffffu, fin, i));
    float gs = 0.f;
    #pragma unroll
    for (int i = 0; i < NTAGS; i++)
        gs += __expf(__shfl_sync(0xffffffffu, fin, i) - gmax);
    float denom = gmax + __logf(gs);

    if (lane == 0) {
        int l0 = lab[0]; int t0 = (l0 == -100) ? 0 : l0;
        int seq_end = cnt - 1;
        int le = lab[seq_end]; int te = (le == -100) ? 0 : le;
        float num = part + cstart[t0] + lg[t0] + cend[te];
        nmd[b] = num - denom;
    }
}

__global__ __launch_bounds__(32) void loss_kernel(
    const float* __restrict__ nmd, float* __restrict__ out)
{
    int lane = threadIdx.x;
    float v = (lane < BATCH) ? nmd[lane] : 0.f;
    #pragma unroll
    for (int o = 16; o > 0; o >>= 1) v += __shfl_xor_sync(0xffffffffu, v, o);
    if (lane == 0) out[0] = -(v * (1.0f / BATCH));
}

// ---------------------------------------------------------------------------
// Launcher
// ---------------------------------------------------------------------------
extern "C" void kernel_launch(void* const* d_in, const int* in_sizes, int n_in,
                              void* d_out, int out_size)
{
    const int*   input_ids = (const int*)d_in[0];
    const int*   amask     = (const int*)d_in[1];
    const int*   labels    = (const int*)d_in[2];
    const float* word_emb  = (const float*)d_in[3];
    const float* pos_emb   = (const float*)d_in[4];
    const float* eln_s     = (const float*)d_in[5];
    const float* eln_b     = (const float*)d_in[6];
    const float* Wqkv      = (const float*)d_in[7];
    const float* bqkv      = (const float*)d_in[8];
    const float* Wo        = (const float*)d_in[9];
    const float* bo        = (const float*)d_in[10];
    const float* ln1s      = (const float*)d_in[11];
    const float* ln1b      = (const float*)d_in[12];
    const float* Wff1      = (const float*)d_in[13];
    const float* bff1      = (const float*)d_in[14];
    const float* Wff2      = (const float*)d_in[15];
    const float* bff2      = (const float*)d_in[16];
    const float* ln2s      = (const float*)d_in[17];
    const float* ln2b      = (const float*)d_in[18];
    const float* Wcls      = (const float*)d_in[19];
    const float* bcls      = (const float*)d_in[20];
    const float* cstart    = (const float*)d_in[21];
    const float* cend      = (const float*)d_in[22];
    const float* ctrans    = (const float*)d_in[23];
    float* out = (float*)d_out;

    float *x, *qkv, *attn, *ffn, *tmp, *nmd, *w;
    cudaGetSymbolAddress((void**)&x,    g_x);
    cudaGetSymbolAddress((void**)&qkv,  g_qkv);
    cudaGetSymbolAddress((void**)&attn, g_attn);
    cudaGetSymbolAddress((void**)&ffn,  g_ffn);
    cudaGetSymbolAddress((void**)&tmp,  g_tmp);
    cudaGetSymbolAddress((void**)&nmd,  g_nmd);
    cudaGetSymbolAddress((void**)&w,    g_w);

    cudaFuncSetAttribute(gemm_tc_kernel,
        cudaFuncAttributeMaxDynamicSharedMemorySize, GEMM_DSMEM);
    cudaFuncSetAttribute(attn_kernel,
        cudaFuncAttributeMaxDynamicSharedMemorySize, ATN_SMEM);

    // one-shot weight tf32 rounding
    conv_tf32_kernel<<<592, 256>>>(Wqkv, w + W_QKV_OFF, W_QKV_SZ / 4);
    conv_tf32_kernel<<<592, 256>>>(Wo,   w + W_WO_OFF,  W_WO_SZ / 4);
    conv_tf32_kernel<<<592, 256>>>(Wff1, w + W_FF1_OFF, W_FF1_SZ / 4);
    conv_tf32_kernel<<<592, 256>>>(Wff2, w + W_FF2_OFF, W_FF2_SZ / 4);

    embed_ln_kernel<<<NTOK / 8, 256>>>(input_ids, word_emb, pos_emb, eln_s, eln_b, x);

    for (int L = 0; L < NLAYER; L++) {
        gemm_tc_kernel<<<dim3(3 * HID / 128, NTOK / 128), 256, GEMM_DSMEM>>>(
            x, w + W_QKV_OFF + (size_t)L * HID * 3 * HID,
            bqkv + (size_t)L * 3 * HID, qkv, NTOK, 3 * HID, HID, 0);

        attn_kernel<<<BATCH * NHEAD, 256, ATN_SMEM>>>(qkv, amask, attn);

        gemm_tc_kernel<<<dim3(HID / 128, NTOK / 128), 256, GEMM_DSMEM>>>(
            attn, w + W_WO_OFF + (size_t)L * HID * HID,
            bo + (size_t)L * HID, tmp, NTOK, HID, HID, 0);

        resid_ln_kernel<<<NTOK / 8, 256>>>(x, tmp,
            ln1s + (size_t)L * HID, ln1b + (size_t)L * HID);

        gemm_tc_kernel<<<dim3(FFN / 128, NTOK / 128), 256, GEMM_DSMEM>>>(
            x, w + W_FF1_OFF + (size_t)L * HID * FFN,
            bff1 + (size_t)L * FFN, ffn, NTOK, FFN, HID, 1);

        gemm_tc_kernel<<<dim3(HID / 128, NTOK / 128), 256, GEMM_DSMEM>>>(
            ffn, w + W_FF2_OFF + (size_t)L * FFN * HID,
            bff2 + (size_t)L * HID, tmp, NTOK, HID, FFN, 0);

        resid_ln_kernel<<<NTOK / 8, 256>>>(x, tmp,
            ln2s + (size_t)L * HID, ln2b + (size_t)L * HID);
    }

    cls_kernel<<<NTOK / 8, 256>>>(x, Wcls, bcls, out + 1);
    crf_kernel<<<BATCH, 32>>>(out + 1, labels, cstart, cend, ctrans, nmd);
    loss_kernel<<<1, 32>>>(nmd, out);
}